// round 1
// baseline (speedup 1.0000x reference)
#include <cuda_runtime.h>
#include <math.h>

#define BATCH 16384
#define NTAB  26
#define NROWSZ 100000
#define EMBD  128
#define ZDIM  480   // 479 padded to 480 (pad column zeroed)

// ---------------- scratch (device globals: allocation-free) ----------------
__device__ float g_x512[BATCH * 512];
__device__ float g_x256[BATCH * 256];
__device__ float g_x128[BATCH * 128];
__device__ float g_z   [BATCH * ZDIM];
__device__ float g_h1  [BATCH * 1024];
__device__ float g_h2  [BATCH * 1024];
__device__ float g_h3  [BATCH * 512];
__device__ float g_h4  [BATCH * 256];
__device__ float g_w0p [1024 * ZDIM];   // tw0 padded 479 -> 480

// ---------------- bottom MLP layer 0: [B,13] @ [512,13]^T ----------------
__global__ void bot0_kernel(const float* __restrict__ x,
                            const float* __restrict__ W,
                            const float* __restrict__ bias,
                            float* __restrict__ out) {
    int b = blockIdx.x;
    __shared__ float xs[13];
    if (threadIdx.x < 13) xs[threadIdx.x] = x[b * 13 + threadIdx.x];
    __syncthreads();
    int n = threadIdx.x;          // 512 threads
    float s = bias[n];
    const float* w = W + n * 13;
#pragma unroll
    for (int k = 0; k < 13; k++) s = fmaf(xs[k], w[k], s);
    out[(size_t)b * 512 + n] = fmaxf(s, 0.0f);
}

// ---------------- pad tw0 [1024,479] -> g_w0p [1024,480] ----------------
__global__ void padw0_kernel(const float* __restrict__ w) {
    int idx = blockIdx.x * blockDim.x + threadIdx.x;   // 1024*480
    int n = idx / ZDIM, k = idx - n * ZDIM;
    g_w0p[idx] = (k < 479) ? w[n * 479 + k] : 0.0f;
}

// ---------------- generic SGEMM: C = relu(A[M,K] @ W[N,K]^T + bias) ----------------
// BM=BN=128, BK=16, 256 threads, 8x8 per thread. M%128==0, N%128==0, K%16==0.
__global__ __launch_bounds__(256, 2)
void sgemm_bias_relu(const float* __restrict__ A, const float* __restrict__ W,
                     const float* __restrict__ bias, float* __restrict__ C,
                     int M, int N, int K) {
    __shared__ float As[16][128];
    __shared__ float Ws[16][128];
    const int tid = threadIdx.x;
    const int bm = blockIdx.y * 128;
    const int bn = blockIdx.x * 128;
    const int tm = (tid >> 4) * 8;        // 0..120
    const int tn = (tid & 15) * 8;        // 0..120

    float acc[8][8];
#pragma unroll
    for (int i = 0; i < 8; i++)
#pragma unroll
        for (int j = 0; j < 8; j++) acc[i][j] = 0.0f;

    for (int k0 = 0; k0 < K; k0 += 16) {
#pragma unroll
        for (int i = 0; i < 2; i++) {
            int idx = tid + i * 256;
            int r = idx >> 2, c4 = (idx & 3) * 4;
            float4 v = *reinterpret_cast<const float4*>(&A[(size_t)(bm + r) * K + k0 + c4]);
            As[c4 + 0][r] = v.x; As[c4 + 1][r] = v.y; As[c4 + 2][r] = v.z; As[c4 + 3][r] = v.w;
        }
#pragma unroll
        for (int i = 0; i < 2; i++) {
            int idx = tid + i * 256;
            int r = idx >> 2, c4 = (idx & 3) * 4;
            float4 v = *reinterpret_cast<const float4*>(&W[(size_t)(bn + r) * K + k0 + c4]);
            Ws[c4 + 0][r] = v.x; Ws[c4 + 1][r] = v.y; Ws[c4 + 2][r] = v.z; Ws[c4 + 3][r] = v.w;
        }
        __syncthreads();
#pragma unroll
        for (int k = 0; k < 16; k++) {
            float a[8], w[8];
#pragma unroll
            for (int j = 0; j < 8; j++) a[j] = As[k][tm + j];
#pragma unroll
            for (int j = 0; j < 8; j++) w[j] = Ws[k][tn + j];
#pragma unroll
            for (int x = 0; x < 8; x++)
#pragma unroll
                for (int y = 0; y < 8; y++)
                    acc[x][y] = fmaf(a[x], w[y], acc[x][y]);
        }
        __syncthreads();
    }

    float bv[8];
#pragma unroll
    for (int y = 0; y < 8; y++) bv[y] = bias[bn + tn + y];
#pragma unroll
    for (int x = 0; x < 8; x++) {
        float4 o0, o1;
        o0.x = fmaxf(acc[x][0] + bv[0], 0.f);
        o0.y = fmaxf(acc[x][1] + bv[1], 0.f);
        o0.z = fmaxf(acc[x][2] + bv[2], 0.f);
        o0.w = fmaxf(acc[x][3] + bv[3], 0.f);
        o1.x = fmaxf(acc[x][4] + bv[4], 0.f);
        o1.y = fmaxf(acc[x][5] + bv[5], 0.f);
        o1.z = fmaxf(acc[x][6] + bv[6], 0.f);
        o1.w = fmaxf(acc[x][7] + bv[7], 0.f);
        float* cp = &C[(size_t)(bm + tm + x) * N + bn + tn];
        *reinterpret_cast<float4*>(cp)     = o0;
        *reinterpret_cast<float4*>(cp + 4) = o1;
    }
}

// ---------------- fused gather + interaction ----------------
// One block per sample. T[27][128] in smem: row0 = x128, rows 1..26 gathered
// embeddings. z[b, 0:128] = x; z[b, 128+p] = dot(T[i],T[j]) for tril pair p;
// z[b, 479] = 0.
__global__ __launch_bounds__(256)
void interact_kernel(const float* __restrict__ x128,
                     const float* __restrict__ emb,
                     const int* __restrict__ lS_i,
                     float* __restrict__ z) {
    const int b = blockIdx.x;
    __shared__ float T[27][128];
    const int tid = threadIdx.x;

    // load 27 rows x 32 float4
    for (int idx = tid; idx < 27 * 32; idx += 256) {
        int row = idx >> 5, c = idx & 31;
        const float4* src;
        if (row == 0) {
            src = reinterpret_cast<const float4*>(&x128[(size_t)b * 128]);
        } else {
            int t = row - 1;
            int ix = lS_i[t * BATCH + b];
            src = reinterpret_cast<const float4*>(&emb[((size_t)t * NROWSZ + ix) * EMBD]);
        }
        reinterpret_cast<float4*>(&T[row][0])[c] = src[c];
    }
    __syncthreads();

    float* zb = &z[(size_t)b * ZDIM];
    // copy x into z[0:128]
    if (tid < 32)
        reinterpret_cast<float4*>(zb)[tid] = reinterpret_cast<const float4*>(&T[0][0])[tid];
    if (tid == 0) zb[479] = 0.0f;

    const int warp = tid >> 5, lane = tid & 31;
    for (int p = warp; p < 351; p += 8) {
        int i = (int)((1.0f + sqrtf(1.0f + 8.0f * (float)p)) * 0.5f);
        while (i * (i - 1) / 2 > p) i--;
        while ((i + 1) * i / 2 <= p) i++;
        int j = p - i * (i - 1) / 2;
        float s = 0.0f;
#pragma unroll
        for (int q = 0; q < 4; q++)
            s = fmaf(T[i][lane + 32 * q], T[j][lane + 32 * q], s);
#pragma unroll
        for (int o = 16; o > 0; o >>= 1) s += __shfl_down_sync(0xffffffffu, s, o);
        if (lane == 0) zb[128 + p] = s;
    }
}

// ---------------- top layer 4: [B,256] -> sigmoid dot ----------------
__global__ void top4_kernel(const float* __restrict__ h,
                            const float* __restrict__ W,
                            const float* __restrict__ bias,
                            float* __restrict__ out) {
    int g = blockIdx.x * blockDim.x + threadIdx.x;
    int warp = g >> 5, lane = g & 31;
    if (warp >= BATCH) return;
    const float* hp = h + (size_t)warp * 256;
    float s = 0.0f;
#pragma unroll
    for (int q = 0; q < 8; q++)
        s = fmaf(hp[lane + 32 * q], W[lane + 32 * q], s);
#pragma unroll
    for (int o = 16; o > 0; o >>= 1) s += __shfl_down_sync(0xffffffffu, s, o);
    if (lane == 0) out[warp] = 1.0f / (1.0f + expf(-(s + bias[0])));
}

// ---------------- launch ----------------
extern "C" void kernel_launch(void* const* d_in, const int* in_sizes, int n_in,
                              void* d_out, int out_size) {
    const float* dense_x = (const float*)d_in[0];
    const int*   lS_i    = (const int*)  d_in[2];
    const float* emb     = (const float*)d_in[3];
    const float* bw0 = (const float*)d_in[4];
    const float* bb0 = (const float*)d_in[5];
    const float* bw1 = (const float*)d_in[6];
    const float* bb1 = (const float*)d_in[7];
    const float* bw2 = (const float*)d_in[8];
    const float* bb2 = (const float*)d_in[9];
    const float* tw0 = (const float*)d_in[10];
    const float* tb0 = (const float*)d_in[11];
    const float* tw1 = (const float*)d_in[12];
    const float* tb1 = (const float*)d_in[13];
    const float* tw2 = (const float*)d_in[14];
    const float* tb2 = (const float*)d_in[15];
    const float* tw3 = (const float*)d_in[16];
    const float* tb3 = (const float*)d_in[17];
    const float* tw4 = (const float*)d_in[18];
    const float* tb4 = (const float*)d_in[19];

    static float *p_x512 = nullptr, *p_x256, *p_x128, *p_z, *p_h1, *p_h2, *p_h3, *p_h4, *p_w0p;
    if (!p_x512) {
        cudaGetSymbolAddress((void**)&p_x512, g_x512);
        cudaGetSymbolAddress((void**)&p_x256, g_x256);
        cudaGetSymbolAddress((void**)&p_x128, g_x128);
        cudaGetSymbolAddress((void**)&p_z,    g_z);
        cudaGetSymbolAddress((void**)&p_h1,   g_h1);
        cudaGetSymbolAddress((void**)&p_h2,   g_h2);
        cudaGetSymbolAddress((void**)&p_h3,   g_h3);
        cudaGetSymbolAddress((void**)&p_h4,   g_h4);
        cudaGetSymbolAddress((void**)&p_w0p,  g_w0p);
    }

    // weight pad (cheap; keeps all GEMM K % 16 == 0)
    padw0_kernel<<<(1024 * ZDIM) / 256, 256>>>(tw0);

    // bottom MLP
    bot0_kernel<<<BATCH, 512>>>(dense_x, bw0, bb0, p_x512);
    sgemm_bias_relu<<<dim3(256 / 128, BATCH / 128), 256>>>(p_x512, bw1, bb1, p_x256, BATCH, 256, 512);
    sgemm_bias_relu<<<dim3(128 / 128, BATCH / 128), 256>>>(p_x256, bw2, bb2, p_x128, BATCH, 128, 256);

    // gather + interaction -> z[B,480]
    interact_kernel<<<BATCH, 256>>>(p_x128, emb, lS_i, p_z);

    // top MLP
    sgemm_bias_relu<<<dim3(1024 / 128, BATCH / 128), 256>>>(p_z,  p_w0p, tb0, p_h1, BATCH, 1024, ZDIM);
    sgemm_bias_relu<<<dim3(1024 / 128, BATCH / 128), 256>>>(p_h1, tw1,   tb1, p_h2, BATCH, 1024, 1024);
    sgemm_bias_relu<<<dim3(512  / 128, BATCH / 128), 256>>>(p_h2, tw2,   tb2, p_h3, BATCH, 512, 1024);
    sgemm_bias_relu<<<dim3(256  / 128, BATCH / 128), 256>>>(p_h3, tw3,   tb3, p_h4, BATCH, 256, 512);

    top4_kernel<<<(BATCH * 32) / 256, 256>>>(p_h4, tw4, tb4, (float*)d_out);
}

// round 2
// speedup vs baseline: 1.7001x; 1.7001x over previous
#include <cuda_runtime.h>
#include <math.h>
#include <stdint.h>

#define BATCH 16384
#define NTAB  26
#define NROWSZ 100000
#define EMBD  128
#define ZDIM  480   // 479 padded to 480 (pad column zeroed)

// ---------------- scratch (device globals: allocation-free) ----------------
__device__ float g_x512[BATCH * 512];
__device__ float g_x256[BATCH * 256];
__device__ float g_x128[BATCH * 128];
__device__ float g_z   [BATCH * ZDIM];
__device__ float g_h1  [BATCH * 1024];
__device__ float g_h2  [BATCH * 1024];
__device__ float g_h3  [BATCH * 512];
__device__ float g_h4  [BATCH * 256];
__device__ float g_w0p [1024 * ZDIM];   // tw0 padded 479 -> 480

// ---------------- helpers ----------------
__device__ __forceinline__ float to_tf32(float x) {
    float r;
    asm("cvt.rna.tf32.f32 %0, %1;" : "=f"(r) : "f"(x));
    return r;
}

// ---------------- bottom MLP layer 0: [B,13] @ [512,13]^T ----------------
__global__ void bot0_kernel(const float* __restrict__ x,
                            const float* __restrict__ W,
                            const float* __restrict__ bias,
                            float* __restrict__ out) {
    int b = blockIdx.x;
    __shared__ float xs[13];
    if (threadIdx.x < 13) xs[threadIdx.x] = x[b * 13 + threadIdx.x];
    __syncthreads();
    int n = threadIdx.x;          // 512 threads
    float s = bias[n];
    const float* w = W + n * 13;
#pragma unroll
    for (int k = 0; k < 13; k++) s = fmaf(xs[k], w[k], s);
    out[(size_t)b * 512 + n] = fmaxf(s, 0.0f);
}

// ---------------- pad tw0 [1024,479] -> g_w0p [1024,480] ----------------
__global__ void padw0_kernel(const float* __restrict__ w) {
    int idx = blockIdx.x * blockDim.x + threadIdx.x;   // 1024*480
    int n = idx / ZDIM, k = idx - n * ZDIM;
    g_w0p[idx] = (k < 479) ? w[n * 479 + k] : 0.0f;
}

// ---------------- TF32 tensor-core GEMM ----------------
// C = relu(A[M,K] @ W[N,K]^T + bias), tf32 inputs (rna-rounded), fp32 accum.
// Block tile 128x128, 256 threads = 8 warps (4 along M x 2 along N),
// warp tile 32(M) x 64(N) via m16n8k8 mma. K chunks of 16, double-buffered.
// Requires M%128==0, N%128==0, K%16==0.
__global__ __launch_bounds__(256, 2)
void gemm_tf32_bias_relu(const float* __restrict__ A, const float* __restrict__ W,
                         const float* __restrict__ bias, float* __restrict__ C,
                         int M, int N, int K) {
    __shared__ float As[2][16][132];   // [k][m], padded
    __shared__ float Bs[2][16][132];   // [k][n], padded

    const int tid  = threadIdx.x;
    const int lane = tid & 31;
    const int warp = tid >> 5;
    const int bm = blockIdx.y * 128;
    const int bn = blockIdx.x * 128;
    const int wm = (warp & 3) * 32;     // warp M offset within tile
    const int wn = (warp >> 2) * 64;    // warp N offset within tile

    float acc[2][8][4];
#pragma unroll
    for (int t = 0; t < 2; t++)
#pragma unroll
        for (int u = 0; u < 8; u++)
#pragma unroll
            for (int v = 0; v < 4; v++) acc[t][u][v] = 0.0f;

    // loader mapping: 512 float4 groups per tile (128 rows x 4 groups)
    const int g0 = tid * 2;
    const int m0 = g0 >> 2,        kq0 = (g0 & 3) * 4;
    const int m1 = (g0 + 1) >> 2,  kq1 = ((g0 + 1) & 3) * 4;

    float4 ra0, ra1, rb0, rb1;

#define FETCH(k0)                                                                 \
    do {                                                                          \
        ra0 = *reinterpret_cast<const float4*>(&A[(size_t)(bm + m0) * K + (k0) + kq0]); \
        ra1 = *reinterpret_cast<const float4*>(&A[(size_t)(bm + m1) * K + (k0) + kq1]); \
        rb0 = *reinterpret_cast<const float4*>(&W[(size_t)(bn + m0) * K + (k0) + kq0]); \
        rb1 = *reinterpret_cast<const float4*>(&W[(size_t)(bn + m1) * K + (k0) + kq1]); \
    } while (0)

#define STAGE(buf)                                                                \
    do {                                                                          \
        As[buf][kq0 + 0][m0] = to_tf32(ra0.x); As[buf][kq0 + 1][m0] = to_tf32(ra0.y); \
        As[buf][kq0 + 2][m0] = to_tf32(ra0.z); As[buf][kq0 + 3][m0] = to_tf32(ra0.w); \
        As[buf][kq1 + 0][m1] = to_tf32(ra1.x); As[buf][kq1 + 1][m1] = to_tf32(ra1.y); \
        As[buf][kq1 + 2][m1] = to_tf32(ra1.z); As[buf][kq1 + 3][m1] = to_tf32(ra1.w); \
        Bs[buf][kq0 + 0][m0] = to_tf32(rb0.x); Bs[buf][kq0 + 1][m0] = to_tf32(rb0.y); \
        Bs[buf][kq0 + 2][m0] = to_tf32(rb0.z); Bs[buf][kq0 + 3][m0] = to_tf32(rb0.w); \
        Bs[buf][kq1 + 0][m1] = to_tf32(rb1.x); Bs[buf][kq1 + 1][m1] = to_tf32(rb1.y); \
        Bs[buf][kq1 + 2][m1] = to_tf32(rb1.z); Bs[buf][kq1 + 3][m1] = to_tf32(rb1.w); \
    } while (0)

    const int nch = K >> 4;
    FETCH(0);
    STAGE(0);
    __syncthreads();

    for (int c = 0; c < nch; c++) {
        const int buf = c & 1;
        if (c + 1 < nch) FETCH((c + 1) << 4);

        // compute on buf: two k8 steps
#pragma unroll
        for (int ks = 0; ks < 2; ks++) {
            const int k = ks * 8;
            uint32_t a[2][4];
#pragma unroll
            for (int t = 0; t < 2; t++) {
                int r0 = wm + t * 16 + (lane >> 2);
                int c0 = k + (lane & 3);
                a[t][0] = __float_as_uint(As[buf][c0][r0]);
                a[t][1] = __float_as_uint(As[buf][c0][r0 + 8]);
                a[t][2] = __float_as_uint(As[buf][c0 + 4][r0]);
                a[t][3] = __float_as_uint(As[buf][c0 + 4][r0 + 8]);
            }
            uint32_t b[8][2];
#pragma unroll
            for (int u = 0; u < 8; u++) {
                int n0 = wn + u * 8 + (lane >> 2);
                int c0 = k + (lane & 3);
                b[u][0] = __float_as_uint(Bs[buf][c0][n0]);
                b[u][1] = __float_as_uint(Bs[buf][c0 + 4][n0]);
            }
#pragma unroll
            for (int t = 0; t < 2; t++)
#pragma unroll
                for (int u = 0; u < 8; u++) {
                    asm volatile(
                        "mma.sync.aligned.m16n8k8.row.col.f32.tf32.tf32.f32 "
                        "{%0,%1,%2,%3}, {%4,%5,%6,%7}, {%8,%9}, {%0,%1,%2,%3};"
                        : "+f"(acc[t][u][0]), "+f"(acc[t][u][1]),
                          "+f"(acc[t][u][2]), "+f"(acc[t][u][3])
                        : "r"(a[t][0]), "r"(a[t][1]), "r"(a[t][2]), "r"(a[t][3]),
                          "r"(b[u][0]), "r"(b[u][1]));
                }
        }

        if (c + 1 < nch) STAGE(buf ^ 1);
        __syncthreads();
    }

    // epilogue: bias + relu, float2 stores
#pragma unroll
    for (int t = 0; t < 2; t++) {
        int row = bm + wm + t * 16 + (lane >> 2);
#pragma unroll
        for (int u = 0; u < 8; u++) {
            int col = bn + wn + u * 8 + (lane & 3) * 2;
            float b0v = bias[col], b1v = bias[col + 1];
            float2 o0, o1;
            o0.x = fmaxf(acc[t][u][0] + b0v, 0.0f);
            o0.y = fmaxf(acc[t][u][1] + b1v, 0.0f);
            o1.x = fmaxf(acc[t][u][2] + b0v, 0.0f);
            o1.y = fmaxf(acc[t][u][3] + b1v, 0.0f);
            *reinterpret_cast<float2*>(&C[(size_t)row * N + col]) = o0;
            *reinterpret_cast<float2*>(&C[(size_t)(row + 8) * N + col]) = o1;
        }
    }
#undef FETCH
#undef STAGE
}

// ---------------- fused gather + interaction ----------------
__global__ __launch_bounds__(256)
void interact_kernel(const float* __restrict__ x128,
                     const float* __restrict__ emb,
                     const int* __restrict__ lS_i,
                     float* __restrict__ z) {
    const int b = blockIdx.x;
    __shared__ float T[27][128];
    const int tid = threadIdx.x;

    for (int idx = tid; idx < 27 * 32; idx += 256) {
        int row = idx >> 5, c = idx & 31;
        const float4* src;
        if (row == 0) {
            src = reinterpret_cast<const float4*>(&x128[(size_t)b * 128]);
        } else {
            int t = row - 1;
            int ix = lS_i[t * BATCH + b];
            src = reinterpret_cast<const float4*>(&emb[((size_t)t * NROWSZ + ix) * EMBD]);
        }
        reinterpret_cast<float4*>(&T[row][0])[c] = src[c];
    }
    __syncthreads();

    float* zb = &z[(size_t)b * ZDIM];
    if (tid < 32)
        reinterpret_cast<float4*>(zb)[tid] = reinterpret_cast<const float4*>(&T[0][0])[tid];
    if (tid == 0) zb[479] = 0.0f;

    const int warp = tid >> 5, lane = tid & 31;
    for (int p = warp; p < 351; p += 8) {
        int i = (int)((1.0f + sqrtf(1.0f + 8.0f * (float)p)) * 0.5f);
        while (i * (i - 1) / 2 > p) i--;
        while ((i + 1) * i / 2 <= p) i++;
        int j = p - i * (i - 1) / 2;
        float s = 0.0f;
#pragma unroll
        for (int q = 0; q < 4; q++)
            s = fmaf(T[i][lane + 32 * q], T[j][lane + 32 * q], s);
#pragma unroll
        for (int o = 16; o > 0; o >>= 1) s += __shfl_down_sync(0xffffffffu, s, o);
        if (lane == 0) zb[128 + p] = s;
    }
}

// ---------------- top layer 4: [B,256] -> sigmoid dot ----------------
__global__ void top4_kernel(const float* __restrict__ h,
                            const float* __restrict__ W,
                            const float* __restrict__ bias,
                            float* __restrict__ out) {
    int g = blockIdx.x * blockDim.x + threadIdx.x;
    int warp = g >> 5, lane = g & 31;
    if (warp >= BATCH) return;
    const float* hp = h + (size_t)warp * 256;
    float s = 0.0f;
#pragma unroll
    for (int q = 0; q < 8; q++)
        s = fmaf(hp[lane + 32 * q], W[lane + 32 * q], s);
#pragma unroll
    for (int o = 16; o > 0; o >>= 1) s += __shfl_down_sync(0xffffffffu, s, o);
    if (lane == 0) out[warp] = 1.0f / (1.0f + expf(-(s + bias[0])));
}

// ---------------- launch ----------------
extern "C" void kernel_launch(void* const* d_in, const int* in_sizes, int n_in,
                              void* d_out, int out_size) {
    const float* dense_x = (const float*)d_in[0];
    const int*   lS_i    = (const int*)  d_in[2];
    const float* emb     = (const float*)d_in[3];
    const float* bw0 = (const float*)d_in[4];
    const float* bb0 = (const float*)d_in[5];
    const float* bw1 = (const float*)d_in[6];
    const float* bb1 = (const float*)d_in[7];
    const float* bw2 = (const float*)d_in[8];
    const float* bb2 = (const float*)d_in[9];
    const float* tw0 = (const float*)d_in[10];
    const float* tb0 = (const float*)d_in[11];
    const float* tw1 = (const float*)d_in[12];
    const float* tb1 = (const float*)d_in[13];
    const float* tw2 = (const float*)d_in[14];
    const float* tb2 = (const float*)d_in[15];
    const float* tw3 = (const float*)d_in[16];
    const float* tb3 = (const float*)d_in[17];
    const float* tw4 = (const float*)d_in[18];
    const float* tb4 = (const float*)d_in[19];

    static float *p_x512 = nullptr, *p_x256, *p_x128, *p_z, *p_h1, *p_h2, *p_h3, *p_h4, *p_w0p;
    if (!p_x512) {
        cudaGetSymbolAddress((void**)&p_x512, g_x512);
        cudaGetSymbolAddress((void**)&p_x256, g_x256);
        cudaGetSymbolAddress((void**)&p_x128, g_x128);
        cudaGetSymbolAddress((void**)&p_z,    g_z);
        cudaGetSymbolAddress((void**)&p_h1,   g_h1);
        cudaGetSymbolAddress((void**)&p_h2,   g_h2);
        cudaGetSymbolAddress((void**)&p_h3,   g_h3);
        cudaGetSymbolAddress((void**)&p_h4,   g_h4);
        cudaGetSymbolAddress((void**)&p_w0p,  g_w0p);
    }

    // weight pad (keeps all GEMM K % 16 == 0)
    padw0_kernel<<<(1024 * ZDIM) / 256, 256>>>(tw0);

    // bottom MLP
    bot0_kernel<<<BATCH, 512>>>(dense_x, bw0, bb0, p_x512);
    gemm_tf32_bias_relu<<<dim3(256 / 128, BATCH / 128), 256>>>(p_x512, bw1, bb1, p_x256, BATCH, 256, 512);
    gemm_tf32_bias_relu<<<dim3(128 / 128, BATCH / 128), 256>>>(p_x256, bw2, bb2, p_x128, BATCH, 128, 256);

    // gather + interaction -> z[B,480]
    interact_kernel<<<BATCH, 256>>>(p_x128, emb, lS_i, p_z);

    // top MLP
    gemm_tf32_bias_relu<<<dim3(1024 / 128, BATCH / 128), 256>>>(p_z,  p_w0p, tb0, p_h1, BATCH, 1024, ZDIM);
    gemm_tf32_bias_relu<<<dim3(1024 / 128, BATCH / 128), 256>>>(p_h1, tw1,   tb1, p_h2, BATCH, 1024, 1024);
    gemm_tf32_bias_relu<<<dim3(512  / 128, BATCH / 128), 256>>>(p_h2, tw2,   tb2, p_h3, BATCH, 512, 1024);
    gemm_tf32_bias_relu<<<dim3(256  / 128, BATCH / 128), 256>>>(p_h3, tw3,   tb3, p_h4, BATCH, 256, 512);

    top4_kernel<<<(BATCH * 32) / 256, 256>>>(p_h4, tw4, tb4, (float*)d_out);
}

// round 4
// speedup vs baseline: 2.3045x; 1.3555x over previous
#include <cuda_runtime.h>
#include <math.h>
#include <stdint.h>

#define BATCH 16384
#define NTAB  26
#define NROWSZ 100000
#define EMBD  128
#define ZDIM  480   // 479 padded to 480 (pad column zeroed)

// ---------------- scratch (device globals: allocation-free) ----------------
__device__ float g_x512[BATCH * 512];
__device__ float g_x256[BATCH * 256];
__device__ float g_x128[BATCH * 128];
__device__ float g_z   [BATCH * ZDIM];
__device__ float g_h1  [BATCH * 1024];
__device__ float g_h2  [BATCH * 1024];
__device__ float g_h3  [BATCH * 512];
__device__ float g_h4  [BATCH * 256];
__device__ float g_w0p [1024 * ZDIM];   // tw0 padded 479 -> 480

// ======================= PTX helpers =======================
__device__ __forceinline__ uint32_t smem_u32(const void* p) {
    uint32_t a;
    asm("{ .reg .u64 t; cvta.to.shared.u64 t, %1; cvt.u32.u64 %0, t; }" : "=r"(a) : "l"(p));
    return a;
}
__device__ __forceinline__ void cpa16(uint32_t dst, const void* src) {
    asm volatile("cp.async.cg.shared.global [%0], [%1], 16;" :: "r"(dst), "l"(src) : "memory");
}
__device__ __forceinline__ void cpa_commit() {
    asm volatile("cp.async.commit_group;" ::: "memory");
}
template <int N>
__device__ __forceinline__ void cpa_wait() {
    asm volatile("cp.async.wait_group %0;" :: "n"(N) : "memory");
}

// ======================= TF32 mma.sync GEMM, cp.async 4-stage =======================
// C = relu(A[M,K] @ W[N,K]^T + bias).  Block tile 128x128, 256 thr = 8 warps
// (4 M x 2 N), warp tile 32x64 via m16n8k8.tf32 (raw fp32 bits, HW-truncated).
// SMEM: As[m][20], Bs[n][20] per stage (pad->20 makes fragment LDS conflict-free,
// rows 16B-aligned for cp.async). Requires M%128==0, N%128==0, K%16==0.
#define RPAD 20
#define STG_FLOATS (2 * 128 * RPAD)          // A + B, one stage
#define NSTAGE 4

__global__ __launch_bounds__(256, 2)
void gemm_tf32_cpa(const float* __restrict__ A, const float* __restrict__ W,
                   const float* __restrict__ bias, float* __restrict__ C,
                   int N, int K) {
    extern __shared__ float sm[];

    const int tid  = threadIdx.x;
    const int lane = tid & 31;
    const int warp = tid >> 5;
    const int bm = blockIdx.y * 128;
    const int bn = blockIdx.x * 128;
    const int wm = (warp & 3) * 32;
    const int wn = (warp >> 2) * 64;

    const uint32_t smb = smem_u32(sm);

    float acc[2][8][4];
#pragma unroll
    for (int t = 0; t < 2; t++)
#pragma unroll
        for (int u = 0; u < 8; u++)
#pragma unroll
            for (int v = 0; v < 4; v++) acc[t][u][v] = 0.0f;

    // loader: 1024 cp.async per stage (A: 128 rows x 4 16B-chunks; B same).
    // this thread's 4 assignments, precomputed.
    int l_row[4], l_ck[4];
    const float* l_src[4];
#pragma unroll
    for (int i = 0; i < 4; i++) {
        int idx = tid + i * 256;            // 0..1023
        int isB = idx >> 9;                 // 0: A, 1: B
        int j = idx & 511;
        l_row[i] = j >> 2;
        l_ck[i]  = j & 3;
        l_src[i] = isB ? (W + (size_t)(bn + l_row[i]) * K + l_ck[i] * 4)
                       : (A + (size_t)(bm + l_row[i]) * K + l_ck[i] * 4);
    }
    uint32_t l_dst[4];
#pragma unroll
    for (int i = 0; i < 4; i++) {
        int idx = tid + i * 256;
        int isB = idx >> 9;
        l_dst[i] = smb + (uint32_t)(isB * 128 * RPAD + l_row[i] * RPAD + l_ck[i] * 4) * 4u;
    }

    auto issue = [&](int c) {
        const uint32_t so = (uint32_t)((c & (NSTAGE - 1)) * STG_FLOATS) * 4u;
        const int kb = c << 4;
#pragma unroll
        for (int i = 0; i < 4; i++)
            cpa16(l_dst[i] + so, l_src[i] + kb);
        cpa_commit();
    };

    const int NC = K >> 4;

    // prologue
    issue(0); issue(1); issue(2);

    const uint32_t a_base = smb;
    const uint32_t b_base = smb + (uint32_t)(128 * RPAD) * 4u;

    for (int c = 0; c < NC; c++) {
        cpa_wait<2>();
        __syncthreads();

        const uint32_t so = (uint32_t)((c & (NSTAGE - 1)) * STG_FLOATS) * 4u;

#pragma unroll
        for (int ks = 0; ks < 2; ks++) {
            const int k = ks * 8;
            uint32_t a[2][4];
#pragma unroll
            for (int t = 0; t < 2; t++) {
                const int r0 = wm + t * 16 + (lane >> 2);
                const int c0 = k + (lane & 3);
                const uint32_t p0 = a_base + so + (uint32_t)(r0 * RPAD + c0) * 4u;
                asm volatile("ld.shared.b32 %0, [%1];"       : "=r"(a[t][0]) : "r"(p0));
                asm volatile("ld.shared.b32 %0, [%1+640];"   : "=r"(a[t][1]) : "r"(p0));   // +8 rows
                asm volatile("ld.shared.b32 %0, [%1+16];"    : "=r"(a[t][2]) : "r"(p0));   // +4 cols
                asm volatile("ld.shared.b32 %0, [%1+656];"   : "=r"(a[t][3]) : "r"(p0));
            }
            uint32_t b[8][2];
#pragma unroll
            for (int u = 0; u < 8; u++) {
                const int n0 = wn + u * 8 + (lane >> 2);
                const int c0 = k + (lane & 3);
                const uint32_t p0 = b_base + so + (uint32_t)(n0 * RPAD + c0) * 4u;
                asm volatile("ld.shared.b32 %0, [%1];"    : "=r"(b[u][0]) : "r"(p0));
                asm volatile("ld.shared.b32 %0, [%1+16];" : "=r"(b[u][1]) : "r"(p0));
            }
#pragma unroll
            for (int t = 0; t < 2; t++)
#pragma unroll
                for (int u = 0; u < 8; u++) {
                    asm volatile(
                        "mma.sync.aligned.m16n8k8.row.col.f32.tf32.tf32.f32 "
                        "{%0,%1,%2,%3}, {%4,%5,%6,%7}, {%8,%9}, {%0,%1,%2,%3};"
                        : "+f"(acc[t][u][0]), "+f"(acc[t][u][1]),
                          "+f"(acc[t][u][2]), "+f"(acc[t][u][3])
                        : "r"(a[t][0]), "r"(a[t][1]), "r"(a[t][2]), "r"(a[t][3]),
                          "r"(b[u][0]), "r"(b[u][1]));
                }
        }

        __syncthreads();
        if (c + 3 < NC) issue(c + 3);
        else            cpa_commit();
    }

    // epilogue: bias + relu, float2 stores
#pragma unroll
    for (int t = 0; t < 2; t++) {
        int row = bm + wm + t * 16 + (lane >> 2);
#pragma unroll
        for (int u = 0; u < 8; u++) {
            int col = bn + wn + u * 8 + (lane & 3) * 2;
            float b0v = bias[col], b1v = bias[col + 1];
            float2 o0, o1;
            o0.x = fmaxf(acc[t][u][0] + b0v, 0.0f);
            o0.y = fmaxf(acc[t][u][1] + b1v, 0.0f);
            o1.x = fmaxf(acc[t][u][2] + b0v, 0.0f);
            o1.y = fmaxf(acc[t][u][3] + b1v, 0.0f);
            *reinterpret_cast<float2*>(&C[(size_t)row * N + col]) = o0;
            *reinterpret_cast<float2*>(&C[(size_t)(row + 8) * N + col]) = o1;
        }
    }
}

// ---------------- bottom MLP layer 0: [B,13] @ [512,13]^T ----------------
__global__ void bot0_kernel(const float* __restrict__ x,
                            const float* __restrict__ W,
                            const float* __restrict__ bias,
                            float* __restrict__ out) {
    int b = blockIdx.x;
    __shared__ float xs[13];
    if (threadIdx.x < 13) xs[threadIdx.x] = x[b * 13 + threadIdx.x];
    __syncthreads();
    int n = threadIdx.x;          // 512 threads
    float s = bias[n];
    const float* w = W + n * 13;
#pragma unroll
    for (int k = 0; k < 13; k++) s = fmaf(xs[k], w[k], s);
    out[(size_t)b * 512 + n] = fmaxf(s, 0.0f);
}

// ---------------- pad tw0 [1024,479] -> g_w0p [1024,480] ----------------
__global__ void padw0_kernel(const float* __restrict__ w) {
    int idx = blockIdx.x * blockDim.x + threadIdx.x;   // 1024*480
    int n = idx / ZDIM, k = idx - n * ZDIM;
    g_w0p[idx] = (k < 479) ? w[n * 479 + k] : 0.0f;
}

// ---------------- fused gather + interaction ----------------
__global__ __launch_bounds__(256)
void interact_kernel(const float* __restrict__ x128,
                     const float* __restrict__ emb,
                     const int* __restrict__ lS_i,
                     float* __restrict__ z) {
    const int b = blockIdx.x;
    __shared__ float T[27][128];
    const int tid = threadIdx.x;

    for (int idx = tid; idx < 27 * 32; idx += 256) {
        int row = idx >> 5, c = idx & 31;
        const float4* src;
        if (row == 0) {
            src = reinterpret_cast<const float4*>(&x128[(size_t)b * 128]);
        } else {
            int t = row - 1;
            int ix = lS_i[t * BATCH + b];
            src = reinterpret_cast<const float4*>(&emb[((size_t)t * NROWSZ + ix) * EMBD]);
        }
        reinterpret_cast<float4*>(&T[row][0])[c] = src[c];
    }
    __syncthreads();

    float* zb = &z[(size_t)b * ZDIM];
    if (tid < 32)
        reinterpret_cast<float4*>(zb)[tid] = reinterpret_cast<const float4*>(&T[0][0])[tid];
    if (tid == 0) zb[479] = 0.0f;

    const int warp = tid >> 5, lane = tid & 31;
    for (int p = warp; p < 351; p += 8) {
        int i = (int)((1.0f + sqrtf(1.0f + 8.0f * (float)p)) * 0.5f);
        while (i * (i - 1) / 2 > p) i--;
        while ((i + 1) * i / 2 <= p) i++;
        int j = p - i * (i - 1) / 2;
        float s = 0.0f;
#pragma unroll
        for (int q = 0; q < 4; q++)
            s = fmaf(T[i][lane + 32 * q], T[j][lane + 32 * q], s);
#pragma unroll
        for (int o = 16; o > 0; o >>= 1) s += __shfl_down_sync(0xffffffffu, s, o);
        if (lane == 0) zb[128 + p] = s;
    }
}

// ---------------- top layer 4: [B,256] -> sigmoid dot ----------------
__global__ void top4_kernel(const float* __restrict__ h,
                            const float* __restrict__ W,
                            const float* __restrict__ bias,
                            float* __restrict__ out) {
    int g = blockIdx.x * blockDim.x + threadIdx.x;
    int warp = g >> 5, lane = g & 31;
    if (warp >= BATCH) return;
    const float* hp = h + (size_t)warp * 256;
    float s = 0.0f;
#pragma unroll
    for (int q = 0; q < 8; q++)
        s = fmaf(hp[lane + 32 * q], W[lane + 32 * q], s);
#pragma unroll
    for (int o = 16; o > 0; o >>= 1) s += __shfl_down_sync(0xffffffffu, s, o);
    if (lane == 0) out[warp] = 1.0f / (1.0f + expf(-(s + bias[0])));
}

// ---------------- launch ----------------
static const int GEMM_SMEM = NSTAGE * STG_FLOATS * 4;   // 4 * 20480 B = 81920

extern "C" void kernel_launch(void* const* d_in, const int* in_sizes, int n_in,
                              void* d_out, int out_size) {
    const float* dense_x = (const float*)d_in[0];
    const int*   lS_i    = (const int*)  d_in[2];
    const float* emb     = (const float*)d_in[3];
    const float* bw0 = (const float*)d_in[4];
    const float* bb0 = (const float*)d_in[5];
    const float* bw1 = (const float*)d_in[6];
    const float* bb1 = (const float*)d_in[7];
    const float* bw2 = (const float*)d_in[8];
    const float* bb2 = (const float*)d_in[9];
    const float* tw0 = (const float*)d_in[10];
    const float* tb0 = (const float*)d_in[11];
    const float* tw1 = (const float*)d_in[12];
    const float* tb1 = (const float*)d_in[13];
    const float* tw2 = (const float*)d_in[14];
    const float* tb2 = (const float*)d_in[15];
    const float* tw3 = (const float*)d_in[16];
    const float* tb3 = (const float*)d_in[17];
    const float* tw4 = (const float*)d_in[18];
    const float* tb4 = (const float*)d_in[19];

    static float *p_x512 = nullptr, *p_x256, *p_x128, *p_z, *p_h1, *p_h2, *p_h3, *p_h4, *p_w0p;
    if (!p_x512) {
        cudaGetSymbolAddress((void**)&p_x512, g_x512);
        cudaGetSymbolAddress((void**)&p_x256, g_x256);
        cudaGetSymbolAddress((void**)&p_x128, g_x128);
        cudaGetSymbolAddress((void**)&p_z,    g_z);
        cudaGetSymbolAddress((void**)&p_h1,   g_h1);
        cudaGetSymbolAddress((void**)&p_h2,   g_h2);
        cudaGetSymbolAddress((void**)&p_h3,   g_h3);
        cudaGetSymbolAddress((void**)&p_h4,   g_h4);
        cudaGetSymbolAddress((void**)&p_w0p,  g_w0p);
        cudaFuncSetAttribute(gemm_tf32_cpa, cudaFuncAttributeMaxDynamicSharedMemorySize, GEMM_SMEM);
    }

    // weight pad (keeps all GEMM K % 16 == 0)
    padw0_kernel<<<(1024 * ZDIM) / 256, 256>>>(tw0);

    // bottom MLP
    bot0_kernel<<<BATCH, 512>>>(dense_x, bw0, bb0, p_x512);
    gemm_tf32_cpa<<<dim3(2, 128), 256, GEMM_SMEM>>>(p_x512, bw1, bb1, p_x256, 256, 512);
    gemm_tf32_cpa<<<dim3(1, 128), 256, GEMM_SMEM>>>(p_x256, bw2, bb2, p_x128, 128, 256);

    // gather + interaction -> z[B,480]
    interact_kernel<<<BATCH, 256>>>(p_x128, emb, lS_i, p_z);

    // top MLP
    gemm_tf32_cpa<<<dim3(8, 128), 256, GEMM_SMEM>>>(p_z,  p_w0p, tb0, p_h1, 1024, ZDIM);
    gemm_tf32_cpa<<<dim3(8, 128), 256, GEMM_SMEM>>>(p_h1, tw1,   tb1, p_h2, 1024, 1024);
    gemm_tf32_cpa<<<dim3(4, 128), 256, GEMM_SMEM>>>(p_h2, tw2,   tb2, p_h3, 512, 1024);
    gemm_tf32_cpa<<<dim3(2, 128), 256, GEMM_SMEM>>>(p_h3, tw3,   tb3, p_h4, 256, 512);

    top4_kernel<<<(BATCH * 32) / 256, 256>>>(p_h4, tw4, tb4, (float*)d_out);
}

// round 5
// speedup vs baseline: 3.3410x; 1.4498x over previous
#include <cuda_runtime.h>
#include <cuda_bf16.h>
#include <math.h>
#include <stdint.h>

#define BATCH 16384
#define NTAB  26
#define NROWSZ 100000
#define EMBD  128
#define ZDIM  512   // 479 padded to 512 (pad columns zeroed)

typedef __nv_bfloat16 bf16;

// ---------------- scratch (device globals: allocation-free) ----------------
__device__ bf16 g_x512[BATCH * 512];
__device__ bf16 g_x256[BATCH * 256];
__device__ bf16 g_x128[BATCH * 128];
__device__ bf16 g_z   [BATCH * ZDIM];
__device__ bf16 g_h1  [BATCH * 1024];
__device__ bf16 g_h2  [BATCH * 1024];
__device__ bf16 g_h3  [BATCH * 512];
__device__ bf16 g_h4  [BATCH * 256];
// bf16 weights
__device__ bf16 g_bw1 [256 * 512];
__device__ bf16 g_bw2 [128 * 256];
__device__ bf16 g_w0  [1024 * ZDIM];   // tw0 padded 479 -> 512
__device__ bf16 g_w1  [1024 * 1024];
__device__ bf16 g_w2  [512 * 1024];
__device__ bf16 g_w3  [256 * 512];
__device__ bf16 g_w4  [256];

// ======================= PTX helpers =======================
__device__ __forceinline__ uint32_t smem_u32(const void* p) {
    uint32_t a;
    asm("{ .reg .u64 t; cvta.to.shared.u64 t, %1; cvt.u32.u64 %0, t; }" : "=r"(a) : "l"(p));
    return a;
}
__device__ __forceinline__ void cpa16(uint32_t dst, const void* src) {
    asm volatile("cp.async.cg.shared.global [%0], [%1], 16;" :: "r"(dst), "l"(src) : "memory");
}
__device__ __forceinline__ void cpa_commit() {
    asm volatile("cp.async.commit_group;" ::: "memory");
}
template <int N>
__device__ __forceinline__ void cpa_wait() {
    asm volatile("cp.async.wait_group %0;" :: "n"(N) : "memory");
}
#define LDSM4(r0, r1, r2, r3, addr)                                            \
    asm volatile("ldmatrix.sync.aligned.m8n8.x4.shared.b16 {%0,%1,%2,%3}, [%4];" \
                 : "=r"(r0), "=r"(r1), "=r"(r2), "=r"(r3) : "r"(addr))

// ======================= bf16 mma.sync GEMM, ldmatrix + cp.async =======================
// C(bf16) = relu(A[M,K] @ W[N,K]^T + bias(fp32)), fp32 accumulate.
// Block 128x128, 8 warps (4M x 2N), warp tile 32x64 via m16n8k16.bf16.
// K-chunk = 64 bf16 = 128B rows, XOR swizzle u^(r&7) (cp.async store + ldmatrix load
// both conflict-free). 3 stages x 32KB = 96KB smem -> 2 CTAs/SM.
// Requires M%128==0, N%128==0, K%64==0.
#define NSTG 3
#define STGB 32768

__global__ __launch_bounds__(256, 2)
void gemm_bf16(const bf16* __restrict__ A, const bf16* __restrict__ W,
               const float* __restrict__ bias, bf16* __restrict__ C,
               int N, int K) {
    extern __shared__ char smraw[];
    const uint32_t smb = smem_u32(smraw);

    const int tid  = threadIdx.x;
    const int lane = tid & 31;
    const int warp = tid >> 5;
    const int bm = blockIdx.y * 128;
    const int bn = blockIdx.x * 128;
    const int wm = (warp & 3) * 32;
    const int wn = (warp >> 2) * 64;

    float acc[2][8][4];
#pragma unroll
    for (int t = 0; t < 2; t++)
#pragma unroll
        for (int u = 0; u < 8; u++)
#pragma unroll
            for (int v = 0; v < 4; v++) acc[t][u][v] = 0.0f;

    // ldmatrix row-derived constants
    // A frag t: tiles (thr0-7: m0-7,k0-7)(8-15: m8-15,k0-7)(16-23: m0-7,k8-15)(24-31: m8-15,k8-15)
    int ra[2], rxa[2];
#pragma unroll
    for (int t = 0; t < 2; t++) {
        int row = wm + t * 16 + ((lane >> 3) & 1) * 8 + (lane & 7);
        ra[t]  = row * 128;
        rxa[t] = (row & 7) << 4;
    }
    const int ua = lane >> 4;           // unit add for A (k8 half)
    // B frag group g: tiles (thr0-7: n0-7,k0-7)(8-15: n0-7,k8-15)(16-23: n8-15,k0-7)(24-31: n8-15,k8-15)
    int rb[4], rxb[4];
#pragma unroll
    for (int g = 0; g < 4; g++) {
        int row = wn + g * 16 + ((lane >> 4) & 1) * 8 + (lane & 7);
        rb[g]  = row * 128;
        rxb[g] = (row & 7) << 4;
    }
    const int ub = (lane >> 3) & 1;     // unit add for B

    const int NC = K >> 6;

    auto issue = [&](int c) {
        const uint32_t so = (uint32_t)((c % NSTG) * STGB);
        const int kb = c << 6;
#pragma unroll
        for (int i = 0; i < 8; i++) {
            const int idx = tid + i * 256;           // 0..2047
            const int isB = (i >= 4);
            const int j = idx & 1023;
            const int r = j >> 3, u = j & 7;
            const bf16* src = (isB ? W + (size_t)(bn + r) * K
                                   : A + (size_t)(bm + r) * K) + kb + u * 8;
            const uint32_t d = smb + so + (isB ? 16384u : 0u)
                             + (uint32_t)(r * 128) + (uint32_t)(((u ^ (r & 7)) << 4));
            cpa16(d, src);
        }
        cpa_commit();
    };

    issue(0);
    if (NC > 1) issue(1); else cpa_commit();

    for (int c = 0; c < NC; c++) {
        cpa_wait<1>();
        __syncthreads();

        const uint32_t Ab = smb + (uint32_t)((c % NSTG) * STGB);
        const uint32_t Bb = Ab + 16384u;

#pragma unroll
        for (int ks = 0; ks < 4; ks++) {
            uint32_t a[2][4];
#pragma unroll
            for (int t = 0; t < 2; t++) {
                const uint32_t addr = Ab + ra[t] + ((((ks * 2 + ua) << 4)) ^ rxa[t]);
                LDSM4(a[t][0], a[t][1], a[t][2], a[t][3], addr);
            }
#pragma unroll
            for (int g = 0; g < 4; g++) {
                uint32_t b0, b1, b2, b3;
                const uint32_t addr = Bb + rb[g] + ((((ks * 2 + ub) << 4)) ^ rxb[g]);
                LDSM4(b0, b1, b2, b3, addr);
#pragma unroll
                for (int t = 0; t < 2; t++) {
                    asm volatile(
                        "mma.sync.aligned.m16n8k16.row.col.f32.bf16.bf16.f32 "
                        "{%0,%1,%2,%3}, {%4,%5,%6,%7}, {%8,%9}, {%0,%1,%2,%3};"
                        : "+f"(acc[t][2 * g][0]), "+f"(acc[t][2 * g][1]),
                          "+f"(acc[t][2 * g][2]), "+f"(acc[t][2 * g][3])
                        : "r"(a[t][0]), "r"(a[t][1]), "r"(a[t][2]), "r"(a[t][3]),
                          "r"(b0), "r"(b1));
                    asm volatile(
                        "mma.sync.aligned.m16n8k16.row.col.f32.bf16.bf16.f32 "
                        "{%0,%1,%2,%3}, {%4,%5,%6,%7}, {%8,%9}, {%0,%1,%2,%3};"
                        : "+f"(acc[t][2 * g + 1][0]), "+f"(acc[t][2 * g + 1][1]),
                          "+f"(acc[t][2 * g + 1][2]), "+f"(acc[t][2 * g + 1][3])
                        : "r"(a[t][0]), "r"(a[t][1]), "r"(a[t][2]), "r"(a[t][3]),
                          "r"(b2), "r"(b3));
                }
            }
        }

        if (c + 2 < NC) issue(c + 2);
        else            cpa_commit();
    }

    // epilogue: bias + relu -> bf16
#pragma unroll
    for (int t = 0; t < 2; t++) {
        const int row = bm + wm + t * 16 + (lane >> 2);
#pragma unroll
        for (int u = 0; u < 8; u++) {
            const int col = bn + wn + u * 8 + (lane & 3) * 2;
            const float b0v = bias[col], b1v = bias[col + 1];
            __nv_bfloat162 o0 = __floats2bfloat162_rn(
                fmaxf(acc[t][u][0] + b0v, 0.0f), fmaxf(acc[t][u][1] + b1v, 0.0f));
            __nv_bfloat162 o1 = __floats2bfloat162_rn(
                fmaxf(acc[t][u][2] + b0v, 0.0f), fmaxf(acc[t][u][3] + b1v, 0.0f));
            *reinterpret_cast<__nv_bfloat162*>(&C[(size_t)row * N + col]) = o0;
            *reinterpret_cast<__nv_bfloat162*>(&C[(size_t)(row + 8) * N + col]) = o1;
        }
    }
}

// ---------------- weight conversion ----------------
__global__ void conv_bf16_kernel(const float* __restrict__ src, bf16* __restrict__ dst, int n) {
    int i = blockIdx.x * blockDim.x + threadIdx.x;
    if (i < n) dst[i] = __float2bfloat16_rn(src[i]);
}
// pad tw0 [1024,479] -> g_w0 [1024,512] bf16
__global__ void padw0_kernel(const float* __restrict__ w) {
    int idx = blockIdx.x * blockDim.x + threadIdx.x;   // 1024*512
    int n = idx >> 9, k = idx & 511;
    g_w0[idx] = (k < 479) ? __float2bfloat16_rn(w[n * 479 + k]) : __float2bfloat16_rn(0.0f);
}

// ---------------- bottom MLP layer 0: [B,13] @ [512,13]^T -> bf16 ----------------
__global__ void bot0_kernel(const float* __restrict__ x,
                            const float* __restrict__ W,
                            const float* __restrict__ bias,
                            bf16* __restrict__ out) {
    int b = blockIdx.x;
    __shared__ float xs[13];
    if (threadIdx.x < 13) xs[threadIdx.x] = x[b * 13 + threadIdx.x];
    __syncthreads();
    int n = threadIdx.x;          // 512 threads
    float s = bias[n];
    const float* w = W + n * 13;
#pragma unroll
    for (int k = 0; k < 13; k++) s = fmaf(xs[k], w[k], s);
    out[(size_t)b * 512 + n] = __float2bfloat16_rn(fmaxf(s, 0.0f));
}

// ---------------- fused gather + interaction (fp32 math, bf16 out) ----------------
__global__ __launch_bounds__(256)
void interact_kernel(const bf16* __restrict__ x128,
                     const float* __restrict__ emb,
                     const int* __restrict__ lS_i,
                     bf16* __restrict__ z) {
    const int b = blockIdx.x;
    __shared__ float T[27][128];
    const int tid = threadIdx.x;

    // rows 1..26: gathered embeddings (fp32, float4)
    for (int idx = tid; idx < 26 * 32; idx += 256) {
        int t = idx >> 5, c = idx & 31;
        int ix = lS_i[t * BATCH + b];
        const float4* src = reinterpret_cast<const float4*>(&emb[((size_t)t * NROWSZ + ix) * EMBD]);
        reinterpret_cast<float4*>(&T[t + 1][0])[c] = src[c];
    }
    // row 0: dense x (bf16 -> fp32)
    if (tid < 128) T[0][tid] = __bfloat162float(x128[(size_t)b * 128 + tid]);
    __syncthreads();

    bf16* zb = &z[(size_t)b * ZDIM];
    // z[0:128] = x (raw bf16 copy, 4B units)
    if (tid < 64)
        reinterpret_cast<uint32_t*>(zb)[tid] =
            reinterpret_cast<const uint32_t*>(&x128[(size_t)b * 128])[tid];
    // zero pad cols 479..511
    if (tid >= 64 && tid < 97) zb[479 + (tid - 64)] = __float2bfloat16_rn(0.0f);

    const int warp = tid >> 5, lane = tid & 31;
    for (int p = warp; p < 351; p += 8) {
        int i = (int)((1.0f + sqrtf(1.0f + 8.0f * (float)p)) * 0.5f);
        while (i * (i - 1) / 2 > p) i--;
        while ((i + 1) * i / 2 <= p) i++;
        int j = p - i * (i - 1) / 2;
        float s = 0.0f;
#pragma unroll
        for (int q = 0; q < 4; q++)
            s = fmaf(T[i][lane + 32 * q], T[j][lane + 32 * q], s);
#pragma unroll
        for (int o = 16; o > 0; o >>= 1) s += __shfl_down_sync(0xffffffffu, s, o);
        if (lane == 0) zb[128 + p] = __float2bfloat16_rn(s);
    }
}

// ---------------- top layer 4: [B,256] bf16 -> sigmoid dot ----------------
__global__ void top4_kernel(const bf16* __restrict__ h,
                            const bf16* __restrict__ W,
                            const float* __restrict__ bias,
                            float* __restrict__ out) {
    int g = blockIdx.x * blockDim.x + threadIdx.x;
    int warp = g >> 5, lane = g & 31;
    if (warp >= BATCH) return;
    const bf16* hp = h + (size_t)warp * 256;
    float s = 0.0f;
#pragma unroll
    for (int q = 0; q < 8; q++)
        s = fmaf(__bfloat162float(hp[lane + 32 * q]), __bfloat162float(W[lane + 32 * q]), s);
#pragma unroll
    for (int o = 16; o > 0; o >>= 1) s += __shfl_down_sync(0xffffffffu, s, o);
    if (lane == 0) out[warp] = 1.0f / (1.0f + expf(-(s + bias[0])));
}

// ---------------- launch ----------------
static const int GEMM_SMEM = NSTG * STGB;   // 98304

extern "C" void kernel_launch(void* const* d_in, const int* in_sizes, int n_in,
                              void* d_out, int out_size) {
    const float* dense_x = (const float*)d_in[0];
    const int*   lS_i    = (const int*)  d_in[2];
    const float* emb     = (const float*)d_in[3];
    const float* bw0 = (const float*)d_in[4];
    const float* bb0 = (const float*)d_in[5];
    const float* bw1 = (const float*)d_in[6];
    const float* bb1 = (const float*)d_in[7];
    const float* bw2 = (const float*)d_in[8];
    const float* bb2 = (const float*)d_in[9];
    const float* tw0 = (const float*)d_in[10];
    const float* tb0 = (const float*)d_in[11];
    const float* tw1 = (const float*)d_in[12];
    const float* tb1 = (const float*)d_in[13];
    const float* tw2 = (const float*)d_in[14];
    const float* tb2 = (const float*)d_in[15];
    const float* tw3 = (const float*)d_in[16];
    const float* tb3 = (const float*)d_in[17];
    const float* tw4 = (const float*)d_in[18];
    const float* tb4 = (const float*)d_in[19];

    static bf16 *p_x512 = nullptr, *p_x256, *p_x128, *p_z, *p_h1, *p_h2, *p_h3, *p_h4;
    static bf16 *p_bw1, *p_bw2, *p_w0, *p_w1, *p_w2, *p_w3, *p_w4;
    if (!p_x512) {
        cudaGetSymbolAddress((void**)&p_x512, g_x512);
        cudaGetSymbolAddress((void**)&p_x256, g_x256);
        cudaGetSymbolAddress((void**)&p_x128, g_x128);
        cudaGetSymbolAddress((void**)&p_z,    g_z);
        cudaGetSymbolAddress((void**)&p_h1,   g_h1);
        cudaGetSymbolAddress((void**)&p_h2,   g_h2);
        cudaGetSymbolAddress((void**)&p_h3,   g_h3);
        cudaGetSymbolAddress((void**)&p_h4,   g_h4);
        cudaGetSymbolAddress((void**)&p_bw1,  g_bw1);
        cudaGetSymbolAddress((void**)&p_bw2,  g_bw2);
        cudaGetSymbolAddress((void**)&p_w0,   g_w0);
        cudaGetSymbolAddress((void**)&p_w1,   g_w1);
        cudaGetSymbolAddress((void**)&p_w2,   g_w2);
        cudaGetSymbolAddress((void**)&p_w3,   g_w3);
        cudaGetSymbolAddress((void**)&p_w4,   g_w4);
        cudaFuncSetAttribute(gemm_bf16, cudaFuncAttributeMaxDynamicSharedMemorySize, GEMM_SMEM);
    }

    // weight conversions (bf16)
    padw0_kernel<<<(1024 * ZDIM) / 256, 256>>>(tw0);
    conv_bf16_kernel<<<(256 * 512 + 255) / 256, 256>>>(bw1, p_bw1, 256 * 512);
    conv_bf16_kernel<<<(128 * 256 + 255) / 256, 256>>>(bw2, p_bw2, 128 * 256);
    conv_bf16_kernel<<<(1024 * 1024 + 255) / 256, 256>>>(tw1, p_w1, 1024 * 1024);
    conv_bf16_kernel<<<(512 * 1024 + 255) / 256, 256>>>(tw2, p_w2, 512 * 1024);
    conv_bf16_kernel<<<(256 * 512 + 255) / 256, 256>>>(tw3, p_w3, 256 * 512);
    conv_bf16_kernel<<<1, 256>>>(tw4, p_w4, 256);

    // bottom MLP
    bot0_kernel<<<BATCH, 512>>>(dense_x, bw0, bb0, p_x512);
    gemm_bf16<<<dim3(2, 128), 256, GEMM_SMEM>>>(p_x512, p_bw1, bb1, p_x256, 256, 512);
    gemm_bf16<<<dim3(1, 128), 256, GEMM_SMEM>>>(p_x256, p_bw2, bb2, p_x128, 128, 256);

    // gather + interaction -> z[B,512] bf16
    interact_kernel<<<BATCH, 256>>>(p_x128, emb, lS_i, p_z);

    // top MLP
    gemm_bf16<<<dim3(8, 128), 256, GEMM_SMEM>>>(p_z,  p_w0, tb0, p_h1, 1024, ZDIM);
    gemm_bf16<<<dim3(8, 128), 256, GEMM_SMEM>>>(p_h1, p_w1, tb1, p_h2, 1024, 1024);
    gemm_bf16<<<dim3(4, 128), 256, GEMM_SMEM>>>(p_h2, p_w2, tb2, p_h3, 512, 1024);
    gemm_bf16<<<dim3(2, 128), 256, GEMM_SMEM>>>(p_h3, p_w3, tb3, p_h4, 256, 512);

    top4_kernel<<<(BATCH * 32) / 256, 256>>>(p_h4, p_w4, tb4, (float*)d_out);
}

// round 6
// speedup vs baseline: 3.4813x; 1.0420x over previous
#include <cuda_runtime.h>
#include <cuda_bf16.h>
#include <math.h>
#include <stdint.h>

#define BATCH 16384
#define NTAB  26
#define NROWSZ 100000
#define EMBD  128
#define ZDIM  512   // 479 padded to 512 (pad columns zeroed)

typedef __nv_bfloat16 bf16;

// ---------------- scratch (device globals: allocation-free) ----------------
__device__ bf16 g_x512[BATCH * 512];
__device__ bf16 g_x256[BATCH * 256];
__device__ bf16 g_x128[BATCH * 128];
__device__ bf16 g_z   [BATCH * ZDIM];
__device__ bf16 g_h1  [BATCH * 1024];
__device__ bf16 g_h2  [BATCH * 1024];
__device__ bf16 g_h3  [BATCH * 512];
__device__ bf16 g_h4  [BATCH * 256];
// bf16 weights
__device__ bf16 g_bw1 [256 * 512];
__device__ bf16 g_bw2 [128 * 256];
__device__ bf16 g_w0  [1024 * ZDIM];   // tw0 padded 479 -> 512
__device__ bf16 g_w1  [1024 * 1024];
__device__ bf16 g_w2  [512 * 1024];
__device__ bf16 g_w3  [256 * 512];
__device__ bf16 g_w4  [256];

// ======================= PTX helpers =======================
__device__ __forceinline__ uint32_t smem_u32(const void* p) {
    uint32_t a;
    asm("{ .reg .u64 t; cvta.to.shared.u64 t, %1; cvt.u32.u64 %0, t; }" : "=r"(a) : "l"(p));
    return a;
}
__device__ __forceinline__ void cpa16(uint32_t dst, const void* src) {
    asm volatile("cp.async.cg.shared.global [%0], [%1], 16;" :: "r"(dst), "l"(src) : "memory");
}
__device__ __forceinline__ void cpa_commit() {
    asm volatile("cp.async.commit_group;" ::: "memory");
}
template <int N>
__device__ __forceinline__ void cpa_wait() {
    asm volatile("cp.async.wait_group %0;" :: "n"(N) : "memory");
}
#define LDSM4(r0, r1, r2, r3, addr)                                            \
    asm volatile("ldmatrix.sync.aligned.m8n8.x4.shared.b16 {%0,%1,%2,%3}, [%4];" \
                 : "=r"(r0), "=r"(r1), "=r"(r2), "=r"(r3) : "r"(addr))
#define HMMA16(d, a0, a1, a2, a3, b0, b1)                                      \
    asm volatile(                                                              \
        "mma.sync.aligned.m16n8k16.row.col.f32.bf16.bf16.f32 "                 \
        "{%0,%1,%2,%3}, {%4,%5,%6,%7}, {%8,%9}, {%0,%1,%2,%3};"                \
        : "+f"((d)[0]), "+f"((d)[1]), "+f"((d)[2]), "+f"((d)[3])               \
        : "r"(a0), "r"(a1), "r"(a2), "r"(a3), "r"(b0), "r"(b1))

// ======================= bf16 mma.sync GEMM =======================
// C(bf16) = relu(A[M,K] @ W[N,K]^T + bias(fp32)), fp32 accumulate.
// Block 128x128, 8 warps (4M x 2N), warp tile 32x64 via m16n8k16.bf16.
// K-chunk = 64 bf16 = 128B rows, XOR swizzle u^(r&7).
// Register double-buffered fragments; 3 cp.async stages; K compile-time.
#define NSTG 3
#define STGB 32768

template <int K>
__global__ __launch_bounds__(256, 2)
void gemm_bf16(const bf16* __restrict__ A, const bf16* __restrict__ W,
               const float* __restrict__ bias, bf16* __restrict__ C,
               int N) {
    extern __shared__ char smraw[];
    const uint32_t smb = smem_u32(smraw);

    const int tid  = threadIdx.x;
    const int lane = tid & 31;
    const int warp = tid >> 5;
    const int bm = blockIdx.y * 128;
    const int bn = blockIdx.x * 128;
    const int wm = (warp & 3) * 32;
    const int wn = (warp >> 2) * 64;

    float acc[2][8][4];
#pragma unroll
    for (int t = 0; t < 2; t++)
#pragma unroll
        for (int u = 0; u < 8; u++)
#pragma unroll
            for (int v = 0; v < 4; v++) acc[t][u][v] = 0.0f;

    // ldmatrix per-warp address constants
    int ra[2], rxa[2];
#pragma unroll
    for (int t = 0; t < 2; t++) {
        int row = wm + t * 16 + ((lane >> 3) & 1) * 8 + (lane & 7);
        ra[t]  = row * 128;
        rxa[t] = (row & 7) << 4;
    }
    const int ua = lane >> 4;
    int rb[4], rxb[4];
#pragma unroll
    for (int g = 0; g < 4; g++) {
        int row = wn + g * 16 + ((lane >> 4) & 1) * 8 + (lane & 7);
        rb[g]  = row * 128;
        rxb[g] = (row & 7) << 4;
    }
    const int ub = (lane >> 3) & 1;

    constexpr int NC = K >> 6;

    auto issue = [&](int c) {
        const uint32_t so = (uint32_t)((c % NSTG) * STGB);
        const int kb = c << 6;
#pragma unroll
        for (int i = 0; i < 8; i++) {
            const int idx = tid + i * 256;           // 0..2047
            const int isB = (i >= 4);
            const int j = idx & 1023;
            const int r = j >> 3, u = j & 7;
            const bf16* src = (isB ? W + (size_t)(bn + r) * K
                                   : A + (size_t)(bm + r) * K) + kb + u * 8;
            const uint32_t d = smb + so + (isB ? 16384u : 0u)
                             + (uint32_t)(r * 128) + (uint32_t)(((u ^ (r & 7)) << 4));
            cpa16(d, src);
        }
        cpa_commit();
    };

    issue(0);
    issue(1);

    uint32_t afr[2][2][4];   // [buf][t][reg]
    uint32_t bfr[2][4][4];   // [buf][g][reg]

#pragma unroll 1
    for (int c = 0; c < NC; c++) {
        cpa_wait<1>();
        __syncthreads();

        if (c + 2 < NC) issue(c + 2);
        else            cpa_commit();

        const uint32_t Ab = smb + (uint32_t)((c % NSTG) * STGB);
        const uint32_t Bb = Ab + 16384u;

        // prefetch ks=0 fragments
#pragma unroll
        for (int t = 0; t < 2; t++)
            LDSM4(afr[0][t][0], afr[0][t][1], afr[0][t][2], afr[0][t][3],
                  Ab + ra[t] + (((ua) << 4) ^ rxa[t]));
#pragma unroll
        for (int g = 0; g < 4; g++)
            LDSM4(bfr[0][g][0], bfr[0][g][1], bfr[0][g][2], bfr[0][g][3],
                  Bb + rb[g] + (((ub) << 4) ^ rxb[g]));

#pragma unroll
        for (int ks = 0; ks < 4; ks++) {
            const int cur = ks & 1, nxt = cur ^ 1;
            if (ks < 3) {
#pragma unroll
                for (int t = 0; t < 2; t++)
                    LDSM4(afr[nxt][t][0], afr[nxt][t][1], afr[nxt][t][2], afr[nxt][t][3],
                          Ab + ra[t] + ((((ks + 1) * 2 + ua) << 4) ^ rxa[t]));
#pragma unroll
                for (int g = 0; g < 4; g++)
                    LDSM4(bfr[nxt][g][0], bfr[nxt][g][1], bfr[nxt][g][2], bfr[nxt][g][3],
                          Bb + rb[g] + ((((ks + 1) * 2 + ub) << 4) ^ rxb[g]));
            }
#pragma unroll
            for (int g = 0; g < 4; g++)
#pragma unroll
                for (int t = 0; t < 2; t++) {
                    HMMA16(acc[t][2 * g],
                           afr[cur][t][0], afr[cur][t][1], afr[cur][t][2], afr[cur][t][3],
                           bfr[cur][g][0], bfr[cur][g][1]);
                    HMMA16(acc[t][2 * g + 1],
                           afr[cur][t][0], afr[cur][t][1], afr[cur][t][2], afr[cur][t][3],
                           bfr[cur][g][2], bfr[cur][g][3]);
                }
        }
    }

    // epilogue: bias + relu -> bf16
#pragma unroll
    for (int t = 0; t < 2; t++) {
        const int row = bm + wm + t * 16 + (lane >> 2);
#pragma unroll
        for (int u = 0; u < 8; u++) {
            const int col = bn + wn + u * 8 + (lane & 3) * 2;
            const float b0v = bias[col], b1v = bias[col + 1];
            __nv_bfloat162 o0 = __floats2bfloat162_rn(
                fmaxf(acc[t][u][0] + b0v, 0.0f), fmaxf(acc[t][u][1] + b1v, 0.0f));
            __nv_bfloat162 o1 = __floats2bfloat162_rn(
                fmaxf(acc[t][u][2] + b0v, 0.0f), fmaxf(acc[t][u][3] + b1v, 0.0f));
            *reinterpret_cast<__nv_bfloat162*>(&C[(size_t)row * N + col]) = o0;
            *reinterpret_cast<__nv_bfloat162*>(&C[(size_t)(row + 8) * N + col]) = o1;
        }
    }
}

// ---------------- fused weight prep (ONE launch) ----------------
// region sizes
#define SZ_W0  (1024 * ZDIM)      // padded from tw0 [1024,479]
#define SZ_BW1 (256 * 512)
#define SZ_BW2 (128 * 256)
#define SZ_W1  (1024 * 1024)
#define SZ_W2  (512 * 1024)
#define SZ_W3  (256 * 512)
#define SZ_W4  (256)
#define SZ_ALL (SZ_W0 + SZ_BW1 + SZ_BW2 + SZ_W1 + SZ_W2 + SZ_W3 + SZ_W4)

__global__ void prep_weights(const float* __restrict__ tw0, const float* __restrict__ bw1,
                             const float* __restrict__ bw2, const float* __restrict__ tw1,
                             const float* __restrict__ tw2, const float* __restrict__ tw3,
                             const float* __restrict__ tw4) {
    int i = blockIdx.x * blockDim.x + threadIdx.x;
    if (i >= SZ_ALL) return;
    if (i < SZ_W0) {
        int n = i >> 9, k = i & 511;
        g_w0[i] = (k < 479) ? __float2bfloat16_rn(tw0[n * 479 + k]) : __float2bfloat16_rn(0.0f);
        return;
    }
    i -= SZ_W0;
    if (i < SZ_BW1) { g_bw1[i] = __float2bfloat16_rn(bw1[i]); return; }
    i -= SZ_BW1;
    if (i < SZ_BW2) { g_bw2[i] = __float2bfloat16_rn(bw2[i]); return; }
    i -= SZ_BW2;
    if (i < SZ_W1)  { g_w1[i] = __float2bfloat16_rn(tw1[i]); return; }
    i -= SZ_W1;
    if (i < SZ_W2)  { g_w2[i] = __float2bfloat16_rn(tw2[i]); return; }
    i -= SZ_W2;
    if (i < SZ_W3)  { g_w3[i] = __float2bfloat16_rn(tw3[i]); return; }
    i -= SZ_W3;
    g_w4[i] = __float2bfloat16_rn(tw4[i]);
}

// ---------------- bottom MLP layer 0: [B,13] @ [512,13]^T -> bf16 ----------------
__global__ void bot0_kernel(const float* __restrict__ x,
                            const float* __restrict__ W,
                            const float* __restrict__ bias,
                            bf16* __restrict__ out) {
    int b = blockIdx.x;
    __shared__ float xs[13];
    if (threadIdx.x < 13) xs[threadIdx.x] = x[b * 13 + threadIdx.x];
    __syncthreads();
    int n = threadIdx.x;          // 512 threads
    float s = bias[n];
    const float* w = W + n * 13;
#pragma unroll
    for (int k = 0; k < 13; k++) s = fmaf(xs[k], w[k], s);
    out[(size_t)b * 512 + n] = __float2bfloat16_rn(fmaxf(s, 0.0f));
}

// ---------------- fused gather + interaction (fp32 math, bf16 out) ----------------
__global__ __launch_bounds__(256)
void interact_kernel(const bf16* __restrict__ x128,
                     const float* __restrict__ emb,
                     const int* __restrict__ lS_i,
                     bf16* __restrict__ z) {
    const int b = blockIdx.x;
    __shared__ float T[27][128];
    const int tid = threadIdx.x;

    for (int idx = tid; idx < 26 * 32; idx += 256) {
        int t = idx >> 5, c = idx & 31;
        int ix = lS_i[t * BATCH + b];
        const float4* src = reinterpret_cast<const float4*>(&emb[((size_t)t * NROWSZ + ix) * EMBD]);
        reinterpret_cast<float4*>(&T[t + 1][0])[c] = src[c];
    }
    if (tid < 128) T[0][tid] = __bfloat162float(x128[(size_t)b * 128 + tid]);
    __syncthreads();

    bf16* zb = &z[(size_t)b * ZDIM];
    if (tid < 64)
        reinterpret_cast<uint32_t*>(zb)[tid] =
            reinterpret_cast<const uint32_t*>(&x128[(size_t)b * 128])[tid];
    if (tid >= 64 && tid < 97) zb[479 + (tid - 64)] = __float2bfloat16_rn(0.0f);

    const int warp = tid >> 5, lane = tid & 31;
    for (int p = warp; p < 351; p += 8) {
        int i = (int)((1.0f + sqrtf(1.0f + 8.0f * (float)p)) * 0.5f);
        while (i * (i - 1) / 2 > p) i--;
        while ((i + 1) * i / 2 <= p) i++;
        int j = p - i * (i - 1) / 2;
        float s = 0.0f;
#pragma unroll
        for (int q = 0; q < 4; q++)
            s = fmaf(T[i][lane + 32 * q], T[j][lane + 32 * q], s);
#pragma unroll
        for (int o = 16; o > 0; o >>= 1) s += __shfl_down_sync(0xffffffffu, s, o);
        if (lane == 0) zb[128 + p] = __float2bfloat16_rn(s);
    }
}

// ---------------- top layer 4: [B,256] bf16 -> sigmoid dot ----------------
__global__ void top4_kernel(const bf16* __restrict__ h,
                            const bf16* __restrict__ W,
                            const float* __restrict__ bias,
                            float* __restrict__ out) {
    int g = blockIdx.x * blockDim.x + threadIdx.x;
    int warp = g >> 5, lane = g & 31;
    if (warp >= BATCH) return;
    const bf16* hp = h + (size_t)warp * 256;
    float s = 0.0f;
#pragma unroll
    for (int q = 0; q < 8; q++)
        s = fmaf(__bfloat162float(hp[lane + 32 * q]), __bfloat162float(W[lane + 32 * q]), s);
#pragma unroll
    for (int o = 16; o > 0; o >>= 1) s += __shfl_down_sync(0xffffffffu, s, o);
    if (lane == 0) out[warp] = 1.0f / (1.0f + expf(-(s + bias[0])));
}

// ---------------- launch ----------------
static const int GEMM_SMEM = NSTG * STGB;   // 98304

extern "C" void kernel_launch(void* const* d_in, const int* in_sizes, int n_in,
                              void* d_out, int out_size) {
    const float* dense_x = (const float*)d_in[0];
    const int*   lS_i    = (const int*)  d_in[2];
    const float* emb     = (const float*)d_in[3];
    const float* bw0 = (const float*)d_in[4];
    const float* bb0 = (const float*)d_in[5];
    const float* bw1 = (const float*)d_in[6];
    const float* bb1 = (const float*)d_in[7];
    const float* bw2 = (const float*)d_in[8];
    const float* bb2 = (const float*)d_in[9];
    const float* tw0 = (const float*)d_in[10];
    const float* tb0 = (const float*)d_in[11];
    const float* tw1 = (const float*)d_in[12];
    const float* tb1 = (const float*)d_in[13];
    const float* tw2 = (const float*)d_in[14];
    const float* tb2 = (const float*)d_in[15];
    const float* tw3 = (const float*)d_in[16];
    const float* tb3 = (const float*)d_in[17];
    const float* tw4 = (const float*)d_in[18];
    const float* tb4 = (const float*)d_in[19];

    static bf16 *p_x512 = nullptr, *p_x256, *p_x128, *p_z, *p_h1, *p_h2, *p_h3, *p_h4;
    static bf16 *p_bw1, *p_bw2, *p_w0, *p_w1, *p_w2, *p_w3, *p_w4;
    if (!p_x512) {
        cudaGetSymbolAddress((void**)&p_x512, g_x512);
        cudaGetSymbolAddress((void**)&p_x256, g_x256);
        cudaGetSymbolAddress((void**)&p_x128, g_x128);
        cudaGetSymbolAddress((void**)&p_z,    g_z);
        cudaGetSymbolAddress((void**)&p_h1,   g_h1);
        cudaGetSymbolAddress((void**)&p_h2,   g_h2);
        cudaGetSymbolAddress((void**)&p_h3,   g_h3);
        cudaGetSymbolAddress((void**)&p_h4,   g_h4);
        cudaGetSymbolAddress((void**)&p_bw1,  g_bw1);
        cudaGetSymbolAddress((void**)&p_bw2,  g_bw2);
        cudaGetSymbolAddress((void**)&p_w0,   g_w0);
        cudaGetSymbolAddress((void**)&p_w1,   g_w1);
        cudaGetSymbolAddress((void**)&p_w2,   g_w2);
        cudaGetSymbolAddress((void**)&p_w3,   g_w3);
        cudaGetSymbolAddress((void**)&p_w4,   g_w4);
        cudaFuncSetAttribute(gemm_bf16<256>,  cudaFuncAttributeMaxDynamicSharedMemorySize, GEMM_SMEM);
        cudaFuncSetAttribute(gemm_bf16<512>,  cudaFuncAttributeMaxDynamicSharedMemorySize, GEMM_SMEM);
        cudaFuncSetAttribute(gemm_bf16<1024>, cudaFuncAttributeMaxDynamicSharedMemorySize, GEMM_SMEM);
    }

    // 1: fused weight prep
    prep_weights<<<(SZ_ALL + 255) / 256, 256>>>(tw0, bw1, bw2, tw1, tw2, tw3, tw4);

    // 2: bottom MLP layer 0
    bot0_kernel<<<BATCH, 512>>>(dense_x, bw0, bb0, p_x512);
    // 3,4: bottom GEMMs
    gemm_bf16<512><<<dim3(2, 128), 256, GEMM_SMEM>>>(p_x512, p_bw1, bb1, p_x256, 256);
    gemm_bf16<256><<<dim3(1, 128), 256, GEMM_SMEM>>>(p_x256, p_bw2, bb2, p_x128, 128);

    // 5: gather + interaction -> z[B,512] bf16
    interact_kernel<<<BATCH, 256>>>(p_x128, emb, lS_i, p_z);

    // 6..9: top MLP   (launch #6 = top0 GEMM -> ncu capture target)
    gemm_bf16<512> <<<dim3(8, 128), 256, GEMM_SMEM>>>(p_z,  p_w0, tb0, p_h1, 1024);
    gemm_bf16<1024><<<dim3(8, 128), 256, GEMM_SMEM>>>(p_h1, p_w1, tb1, p_h2, 1024);
    gemm_bf16<1024><<<dim3(4, 128), 256, GEMM_SMEM>>>(p_h2, p_w2, tb2, p_h3, 512);
    gemm_bf16<512> <<<dim3(2, 128), 256, GEMM_SMEM>>>(p_h3, p_w3, tb3, p_h4, 256);

    // 10: final dot + sigmoid
    top4_kernel<<<(BATCH * 32) / 256, 256>>>(p_h4, p_w4, tb4, (float*)d_out);
}

// round 9
// speedup vs baseline: 7.0102x; 2.0137x over previous
#include <cuda_runtime.h>
#include <cuda_bf16.h>
#include <math.h>
#include <stdint.h>

#define BATCH 16384
#define NTAB  26
#define NROWSZ 100000
#define EMBD  128
#define ZDIM  512   // 479 padded to 512 (pad columns zeroed)

typedef __nv_bfloat16 bf16;

// ---------------- scratch (device globals: allocation-free) ----------------
__device__ bf16 g_x512[BATCH * 512];
__device__ bf16 g_x256[BATCH * 256];
__device__ bf16 g_x128[BATCH * 128];
__device__ bf16 g_z   [BATCH * ZDIM];
__device__ bf16 g_h1  [BATCH * 1024];
__device__ bf16 g_h2  [BATCH * 1024];
__device__ bf16 g_h3  [BATCH * 512];
__device__ bf16 g_h4  [BATCH * 256];
// bf16 weights
__device__ bf16 g_bw1 [256 * 512];
__device__ bf16 g_bw2 [128 * 256];
__device__ bf16 g_w0  [1024 * ZDIM];   // tw0 padded 479 -> 512
__device__ bf16 g_w1  [1024 * 1024];
__device__ bf16 g_w2  [512 * 1024];
__device__ bf16 g_w3  [256 * 512];
__device__ bf16 g_w4  [256];

// ======================= PTX helpers =======================
__device__ __forceinline__ uint32_t smem_u32(const void* p) {
    uint32_t a;
    asm("{ .reg .u64 t; cvta.to.shared.u64 t, %1; cvt.u32.u64 %0, t; }" : "=r"(a) : "l"(p));
    return a;
}
__device__ __forceinline__ void cpa16(uint32_t dst, const void* src) {
    asm volatile("cp.async.cg.shared.global [%0], [%1], 16;" :: "r"(dst), "l"(src) : "memory");
}
__device__ __forceinline__ void cpa_commit() {
    asm volatile("cp.async.commit_group;" ::: "memory");
}
template <int N>
__device__ __forceinline__ void cpa_wait() {
    asm volatile("cp.async.wait_group %0;" :: "n"(N) : "memory");
}
__device__ __forceinline__ uint32_t pack_bf16x2(float lo, float hi) {
    uint32_t r;
    asm("cvt.rn.bf16x2.f32 %0, %1, %2;" : "=r"(r) : "f"(hi), "f"(lo));
    return r;
}
#define LDSM4(r0, r1, r2, r3, addr)                                            \
    asm volatile("ldmatrix.sync.aligned.m8n8.x4.shared.b16 {%0,%1,%2,%3}, [%4];" \
                 : "=r"(r0), "=r"(r1), "=r"(r2), "=r"(r3) : "r"(addr))
#define LDSM2(r0, r1, addr)                                                    \
    asm volatile("ldmatrix.sync.aligned.m8n8.x2.shared.b16 {%0,%1}, [%2];"     \
                 : "=r"(r0), "=r"(r1) : "r"(addr))
#define HMMA16(d, a0, a1, a2, a3, b0, b1)                                      \
    asm volatile(                                                              \
        "mma.sync.aligned.m16n8k16.row.col.f32.bf16.bf16.f32 "                 \
        "{%0,%1,%2,%3}, {%4,%5,%6,%7}, {%8,%9}, {%0,%1,%2,%3};"                \
        : "+f"((d)[0]), "+f"((d)[1]), "+f"((d)[2]), "+f"((d)[3])               \
        : "r"(a0), "r"(a1), "r"(a2), "r"(a3), "r"(b0), "r"(b1))

// ======================= bf16 mma.sync GEMM =======================
// C(bf16) = relu(A[M,K] @ W[N,K]^T + bias(fp32)), fp32 accumulate.
// Block 128x128, 8 warps (4M x 2N), warp tile 32x64 via m16n8k16.bf16.
// K-chunk = 64 bf16 = 128B rows, XOR swizzle u^(r&7).
// Pointer-increment cp.async addressing (no per-chunk 64-bit address math).
#define NSTG 3
#define STGB 32768

template <int K>
__global__ __launch_bounds__(256, 2)
void gemm_bf16(const bf16* __restrict__ A, const bf16* __restrict__ W,
               const float* __restrict__ bias, bf16* __restrict__ C,
               int N) {
    extern __shared__ char smraw[];
    const uint32_t smb = smem_u32(smraw);

    const int tid  = threadIdx.x;
    const int lane = tid & 31;
    const int warp = tid >> 5;
    const int bm = blockIdx.y * 128;
    const int bn = blockIdx.x * 128;
    const int wm = (warp & 3) * 32;
    const int wn = (warp >> 2) * 64;

    float acc[2][8][4];
#pragma unroll
    for (int t = 0; t < 2; t++)
#pragma unroll
        for (int u = 0; u < 8; u++)
#pragma unroll
            for (int v = 0; v < 4; v++) acc[t][u][v] = 0.0f;

    // ldmatrix per-warp address constants
    int ra[2], rxa[2];
#pragma unroll
    for (int t = 0; t < 2; t++) {
        int row = wm + t * 16 + ((lane >> 3) & 1) * 8 + (lane & 7);
        ra[t]  = row * 128;
        rxa[t] = (row & 7) << 4;
    }
    const int ua = lane >> 4;
    int rb[4], rxb[4];
#pragma unroll
    for (int g = 0; g < 4; g++) {
        int row = wn + g * 16 + ((lane >> 4) & 1) * 8 + (lane & 7);
        rb[g]  = row * 128;
        rxb[g] = (row & 7) << 4;
    }
    const int ub = (lane >> 3) & 1;

    constexpr int NC = K >> 6;

    // loader bases (thread-fixed); 4 slices per matrix at constant strides
    const int r0 = tid >> 3, u0 = tid & 7;
    const bf16* aP = A + (size_t)(bm + r0) * K + u0 * 8;
    const bf16* wP = W + (size_t)(bn + r0) * K + u0 * 8;
    const uint32_t dOff = smb + (uint32_t)(r0 * 128) + (uint32_t)(((u0 ^ (r0 & 7)) << 4));

    auto issue = [&](uint32_t so, const bf16* a, const bf16* w) {
#pragma unroll
        for (int i = 0; i < 4; i++) cpa16(dOff + so + i * 4096, a + i * (32 * K));
#pragma unroll
        for (int i = 0; i < 4; i++) cpa16(dOff + so + 16384u + i * 4096, w + i * (32 * K));
        cpa_commit();
    };

    issue(0, aP, wP);
    if (NC > 1) issue(STGB, aP + 64, wP + 64); else cpa_commit();
    const bf16* aN = aP + 128;
    const bf16* wN = wP + 128;
    uint32_t soN = 2 * STGB;
    uint32_t soC = 0;

    uint32_t afr[2][2][4];
    uint32_t bfr[2][4][4];

#pragma unroll 1
    for (int c = 0; c < NC; c++) {
        cpa_wait<1>();
        __syncthreads();

        if (c + 2 < NC) {
            issue(soN, aN, wN);
            aN += 64; wN += 64;
            soN += STGB; if (soN == NSTG * STGB) soN = 0;
        } else {
            cpa_commit();
        }

        const uint32_t Ab = smb + soC;
        const uint32_t Bb = Ab + 16384u;
        soC += STGB; if (soC == NSTG * STGB) soC = 0;

        // prefetch ks=0 fragments
#pragma unroll
        for (int t = 0; t < 2; t++)
            LDSM4(afr[0][t][0], afr[0][t][1], afr[0][t][2], afr[0][t][3],
                  Ab + ra[t] + (((ua) << 4) ^ rxa[t]));
#pragma unroll
        for (int g = 0; g < 4; g++)
            LDSM4(bfr[0][g][0], bfr[0][g][1], bfr[0][g][2], bfr[0][g][3],
                  Bb + rb[g] + (((ub) << 4) ^ rxb[g]));

#pragma unroll
        for (int ks = 0; ks < 4; ks++) {
            const int cur = ks & 1, nxt = cur ^ 1;
            if (ks < 3) {
#pragma unroll
                for (int t = 0; t < 2; t++)
                    LDSM4(afr[nxt][t][0], afr[nxt][t][1], afr[nxt][t][2], afr[nxt][t][3],
                          Ab + ra[t] + ((((ks + 1) * 2 + ua) << 4) ^ rxa[t]));
#pragma unroll
                for (int g = 0; g < 4; g++)
                    LDSM4(bfr[nxt][g][0], bfr[nxt][g][1], bfr[nxt][g][2], bfr[nxt][g][3],
                          Bb + rb[g] + ((((ks + 1) * 2 + ub) << 4) ^ rxb[g]));
            }
#pragma unroll
            for (int g = 0; g < 4; g++)
#pragma unroll
                for (int t = 0; t < 2; t++) {
                    HMMA16(acc[t][2 * g],
                           afr[cur][t][0], afr[cur][t][1], afr[cur][t][2], afr[cur][t][3],
                           bfr[cur][g][0], bfr[cur][g][1]);
                    HMMA16(acc[t][2 * g + 1],
                           afr[cur][t][0], afr[cur][t][1], afr[cur][t][2], afr[cur][t][3],
                           bfr[cur][g][2], bfr[cur][g][3]);
                }
        }
    }

    // epilogue: bias + relu -> bf16
#pragma unroll
    for (int t = 0; t < 2; t++) {
        const int row = bm + wm + t * 16 + (lane >> 2);
#pragma unroll
        for (int u = 0; u < 8; u++) {
            const int col = bn + wn + u * 8 + (lane & 3) * 2;
            const float b0v = bias[col], b1v = bias[col + 1];
            uint32_t o0 = pack_bf16x2(fmaxf(acc[t][u][0] + b0v, 0.0f),
                                      fmaxf(acc[t][u][1] + b1v, 0.0f));
            uint32_t o1 = pack_bf16x2(fmaxf(acc[t][u][2] + b0v, 0.0f),
                                      fmaxf(acc[t][u][3] + b1v, 0.0f));
            *reinterpret_cast<uint32_t*>(&C[(size_t)row * N + col]) = o0;
            *reinterpret_cast<uint32_t*>(&C[(size_t)(row + 8) * N + col]) = o1;
        }
    }
}

// ---------------- fused weight prep (ONE launch) ----------------
#define SZ_W0  (1024 * ZDIM)
#define SZ_BW1 (256 * 512)
#define SZ_BW2 (128 * 256)
#define SZ_W1  (1024 * 1024)
#define SZ_W2  (512 * 1024)
#define SZ_W3  (256 * 512)
#define SZ_W4  (256)
#define SZ_ALL (SZ_W0 + SZ_BW1 + SZ_BW2 + SZ_W1 + SZ_W2 + SZ_W3 + SZ_W4)

__global__ void prep_weights(const float* __restrict__ tw0, const float* __restrict__ bw1,
                             const float* __restrict__ bw2, const float* __restrict__ tw1,
                             const float* __restrict__ tw2, const float* __restrict__ tw3,
                             const float* __restrict__ tw4) {
    int i = blockIdx.x * blockDim.x + threadIdx.x;
    if (i >= SZ_ALL) return;
    if (i < SZ_W0) {
        int n = i >> 9, k = i & 511;
        g_w0[i] = (k < 479) ? __float2bfloat16_rn(tw0[n * 479 + k]) : __float2bfloat16_rn(0.0f);
        return;
    }
    i -= SZ_W0;
    if (i < SZ_BW1) { g_bw1[i] = __float2bfloat16_rn(bw1[i]); return; }
    i -= SZ_BW1;
    if (i < SZ_BW2) { g_bw2[i] = __float2bfloat16_rn(bw2[i]); return; }
    i -= SZ_BW2;
    if (i < SZ_W1)  { g_w1[i] = __float2bfloat16_rn(tw1[i]); return; }
    i -= SZ_W1;
    if (i < SZ_W2)  { g_w2[i] = __float2bfloat16_rn(tw2[i]); return; }
    i -= SZ_W2;
    if (i < SZ_W3)  { g_w3[i] = __float2bfloat16_rn(tw3[i]); return; }
    i -= SZ_W3;
    g_w4[i] = __float2bfloat16_rn(tw4[i]);
}

// ---------------- bottom MLP layer 0: 8 samples per block ----------------
#define B0S 8
__global__ __launch_bounds__(512)
void bot0_kernel(const float* __restrict__ x,
                 const float* __restrict__ W,
                 const float* __restrict__ bias,
                 bf16* __restrict__ out) {
    const int b0 = blockIdx.x * B0S;
    __shared__ float Ws[512 * 13];
    __shared__ float xs[B0S][13];
    const int tid = threadIdx.x;

    for (int i = tid; i < 512 * 13; i += 512) Ws[i] = W[i];
    if (tid < B0S * 13) xs[tid / 13][tid % 13] = x[(b0 + tid / 13) * 13 + tid % 13];
    __syncthreads();

    float w[13];
#pragma unroll
    for (int k = 0; k < 13; k++) w[k] = Ws[tid * 13 + k];
    const float bv = bias[tid];
#pragma unroll
    for (int s = 0; s < B0S; s++) {
        float acc = bv;
#pragma unroll
        for (int k = 0; k < 13; k++) acc = fmaf(xs[s][k], w[k], acc);
        out[(size_t)(b0 + s) * 512 + tid] = __float2bfloat16_rn(fmaxf(acc, 0.0f));
    }
}

// ---------------- fused gather + tensor-core interaction ----------------
// One block per sample. T (32x128 bf16, rows 27..31 zero) in smem with 256B
// rows swizzled per 128B half. Z = T @ T^T computed by 8 warps (2 m16 x 4 n8),
// lower-tri entries scattered to z[b, 128+p].
__global__ __launch_bounds__(256)
void interact_kernel(const bf16* __restrict__ x128,
                     const float* __restrict__ emb,
                     const int* __restrict__ lS_i,
                     bf16* __restrict__ z) {
    const int b = blockIdx.x;
    __shared__ __align__(1024) bf16 T[32 * 128];   // 8KB
    const int tid = threadIdx.x, lane = tid & 31, wid = tid >> 5;
    char* Tb = reinterpret_cast<char*>(T);
    bf16* zb = &z[(size_t)b * ZDIM];

    // zero rows 27..31 (5 rows x 256B = 160 x 8B)
    if (tid < 160)
        *reinterpret_cast<uint64_t*>(Tb + (27 + tid / 32) * 256 + (tid % 32) * 8) = 0ull;

    // row 0 = x (bf16, 16 x 16B units; r=0 -> swizzle identity)
    if (tid >= 160 && tid < 176) {
        const int u = tid - 160;
        uint4 v = *reinterpret_cast<const uint4*>(x128 + (size_t)b * 128 + u * 8);
        *reinterpret_cast<uint4*>(Tb + (u << 4)) = v;
    }

    // z[0:128] = x  (64 x 4B), pad zero cols 479..511
    if (tid < 64)
        reinterpret_cast<uint32_t*>(zb)[tid] =
            reinterpret_cast<const uint32_t*>(x128 + (size_t)b * 128)[tid];
    if (tid >= 64 && tid < 97) zb[479 + (tid - 64)] = __float2bfloat16_rn(0.0f);

    // gather rows 1..26 (fp32 -> bf16), 832 float4 tasks
    for (int idx = tid; idx < 26 * 32; idx += 256) {
        const int t = idx >> 5, c = idx & 31;
        const int ix = lS_i[t * BATCH + b];
        const float4 v = *reinterpret_cast<const float4*>(
            &emb[((size_t)t * NROWSZ + ix) * EMBD + c * 4]);
        const int r = t + 1, k = c * 4;
        uint2 pk;
        pk.x = pack_bf16x2(v.x, v.y);
        pk.y = pack_bf16x2(v.z, v.w);
        *reinterpret_cast<uint2*>(
            Tb + r * 256 + ((((k >> 3) ^ (r & 7)) << 4)) + (k & 7) * 2) = pk;
    }
    __syncthreads();

    // Z = T @ T^T ; warp wid: m-half mh = wid&1 (rows mh*16..+15), n-tile nq = wid>>1 (cols nq*8..+7)
    const uint32_t smb = smem_u32(T);
    const int mh = wid & 1, nq = wid >> 1;
    const int raRow = mh * 16 + (lane & 15);
    const uint32_t aBase = smb + raRow * 256;
    const int rxa = raRow & 7;
    const int uaH = lane >> 4;
    const int rbRow = nq * 8 + (lane & 7);
    const uint32_t bBase = smb + rbRow * 256;
    const int rxb = rbRow & 7;
    const int ubH = (lane >> 3) & 1;

    float acc[4] = {0.f, 0.f, 0.f, 0.f};
#pragma unroll
    for (int ks = 0; ks < 8; ks++) {
        uint32_t a0, a1, a2, a3, b0, b1;
        LDSM4(a0, a1, a2, a3, aBase + (((ks * 2 + uaH) ^ rxa) << 4));
        LDSM2(b0, b1,         bBase + (((ks * 2 + ubH) ^ rxb) << 4));
        HMMA16(acc, a0, a1, a2, a3, b0, b1);
    }

    // scatter lower-tri
    const int row0 = mh * 16 + (lane >> 2);
    const int col0 = nq * 8 + (lane & 3) * 2;
#pragma unroll
    for (int v = 0; v < 4; v++) {
        const int i = row0 + (v >> 1) * 8;
        const int j = col0 + (v & 1);
        if (i < 27 && j < i)
            zb[128 + (i * (i - 1)) / 2 + j] = __float2bfloat16_rn(acc[v]);
    }
}

// ---------------- top layer 4: [B,256] bf16 -> sigmoid dot ----------------
__global__ void top4_kernel(const bf16* __restrict__ h,
                            const bf16* __restrict__ W,
                            const float* __restrict__ bias,
                            float* __restrict__ out) {
    int g = blockIdx.x * blockDim.x + threadIdx.x;
    int warp = g >> 5, lane = g & 31;
    if (warp >= BATCH) return;
    const bf16* hp = h + (size_t)warp * 256;
    float s = 0.0f;
#pragma unroll
    for (int q = 0; q < 8; q++)
        s = fmaf(__bfloat162float(hp[lane + 32 * q]), __bfloat162float(W[lane + 32 * q]), s);
#pragma unroll
    for (int o = 16; o > 0; o >>= 1) s += __shfl_down_sync(0xffffffffu, s, o);
    if (lane == 0) out[warp] = 1.0f / (1.0f + expf(-(s + bias[0])));
}

// ---------------- launch ----------------
static const int GEMM_SMEM = NSTG * STGB;   // 98304

extern "C" void kernel_launch(void* const* d_in, const int* in_sizes, int n_in,
                              void* d_out, int out_size) {
    const float* dense_x = (const float*)d_in[0];
    const int*   lS_i    = (const int*)  d_in[2];
    const float* emb     = (const float*)d_in[3];
    const float* bw0 = (const float*)d_in[4];
    const float* bb0 = (const float*)d_in[5];
    const float* bw1 = (const float*)d_in[6];
    const float* bb1 = (const float*)d_in[7];
    const float* bw2 = (const float*)d_in[8];
    const float* bb2 = (const float*)d_in[9];
    const float* tw0 = (const float*)d_in[10];
    const float* tb0 = (const float*)d_in[11];
    const float* tw1 = (const float*)d_in[12];
    const float* tb1 = (const float*)d_in[13];
    const float* tw2 = (const float*)d_in[14];
    const float* tb2 = (const float*)d_in[15];
    const float* tw3 = (const float*)d_in[16];
    const float* tb3 = (const float*)d_in[17];
    const float* tw4 = (const float*)d_in[18];
    const float* tb4 = (const float*)d_in[19];

    static bf16 *p_x512 = nullptr, *p_x256, *p_x128, *p_z, *p_h1, *p_h2, *p_h3, *p_h4;
    static bf16 *p_bw1, *p_bw2, *p_w0, *p_w1, *p_w2, *p_w3, *p_w4;
    if (!p_x512) {
        cudaGetSymbolAddress((void**)&p_x512, g_x512);
        cudaGetSymbolAddress((void**)&p_x256, g_x256);
        cudaGetSymbolAddress((void**)&p_x128, g_x128);
        cudaGetSymbolAddress((void**)&p_z,    g_z);
        cudaGetSymbolAddress((void**)&p_h1,   g_h1);
        cudaGetSymbolAddress((void**)&p_h2,   g_h2);
        cudaGetSymbolAddress((void**)&p_h3,   g_h3);
        cudaGetSymbolAddress((void**)&p_h4,   g_h4);
        cudaGetSymbolAddress((void**)&p_bw1,  g_bw1);
        cudaGetSymbolAddress((void**)&p_bw2,  g_bw2);
        cudaGetSymbolAddress((void**)&p_w0,   g_w0);
        cudaGetSymbolAddress((void**)&p_w1,   g_w1);
        cudaGetSymbolAddress((void**)&p_w2,   g_w2);
        cudaGetSymbolAddress((void**)&p_w3,   g_w3);
        cudaGetSymbolAddress((void**)&p_w4,   g_w4);
        cudaFuncSetAttribute(gemm_bf16<256>,  cudaFuncAttributeMaxDynamicSharedMemorySize, GEMM_SMEM);
        cudaFuncSetAttribute(gemm_bf16<512>,  cudaFuncAttributeMaxDynamicSharedMemorySize, GEMM_SMEM);
        cudaFuncSetAttribute(gemm_bf16<1024>, cudaFuncAttributeMaxDynamicSharedMemorySize, GEMM_SMEM);
    }

    // 1: fused weight prep
    prep_weights<<<(SZ_ALL + 255) / 256, 256>>>(tw0, bw1, bw2, tw1, tw2, tw3, tw4);

    // 2: bottom MLP layer 0
    bot0_kernel<<<BATCH / B0S, 512>>>(dense_x, bw0, bb0, p_x512);
    // 3,4: bottom GEMMs
    gemm_bf16<512><<<dim3(2, 128), 256, GEMM_SMEM>>>(p_x512, p_bw1, bb1, p_x256, 256);
    gemm_bf16<256><<<dim3(1, 128), 256, GEMM_SMEM>>>(p_x256, p_bw2, bb2, p_x128, 128);

    // 5: gather + tensor-core interaction -> z[B,512] bf16
    interact_kernel<<<BATCH, 256>>>(p_x128, emb, lS_i, p_z);

    // 6..9: top MLP
    gemm_bf16<512> <<<dim3(8, 128), 256, GEMM_SMEM>>>(p_z,  p_w0, tb0, p_h1, 1024);
    gemm_bf16<1024><<<dim3(8, 128), 256, GEMM_SMEM>>>(p_h1, p_w1, tb1, p_h2, 1024);
    gemm_bf16<1024><<<dim3(4, 128), 256, GEMM_SMEM>>>(p_h2, p_w2, tb2, p_h3, 512);
    gemm_bf16<512> <<<dim3(2, 128), 256, GEMM_SMEM>>>(p_h3, p_w3, tb3, p_h4, 256);

    // 10: final dot + sigmoid
    top4_kernel<<<(BATCH * 32) / 256, 256>>>(p_h4, p_w4, tb4, (float*)d_out);
}